// round 12
// baseline (speedup 1.0000x reference)
#include <cuda_runtime.h>

#define NN 100000
#define EE 1600000
#define IND 128
#define HIDD 64
#define NC 40

#define NBG 391               // ceil(NN / 256)
#define NTPB 256
#define EGRID 1184
#define ETPB 256
#define EWPB (ETPB / 32)
#define EWARPS (EGRID * EWPB)
#define SCAN_BLKS 391         // ceil(NN/256)

typedef unsigned long long ull;

// ---------------- device scratch ----------------
__device__ float4 g_h0[NN * 16];     // embedding output
__device__ float4 g_h1[NN * 16];     // layer-0 aggregate (raw)
__device__ float4 g_hacc[NN * 16];   // layer-1 aggregate (raw)
__device__ float4 g_wh[NN * 16];
__device__ float  g_ssrc[NN];
__device__ float  g_sdst[NN];
__device__ float  g_pmax_s[NBG];
__device__ float  g_pmax_d[NBG];
__device__ float  g_psum[EGRID];
__device__ int    g_is64;
// CSR
__device__ int2   g_epack[EE];
__device__ int    g_deg[NN];
__device__ int    g_rp[NN];
__device__ int    g_btot[SCAN_BLKS];
__device__ int    g_boff[SCAN_BLKS];
__device__ int    g_rowptr[NN + 1];
__device__ int    g_cursor[NN];
__device__ int    g_csrc[EE];

// ---------------- f32x2 helpers ----------------
__device__ __forceinline__ ull pk2(float a, float b) {
    ull r;
    asm("mov.b64 %0, {%1, %2};" : "=l"(r) : "f"(a), "f"(b));
    return r;
}
__device__ __forceinline__ ull dup2(float a) { return pk2(a, a); }
__device__ __forceinline__ float2 upk2(ull v) {
    float2 r;
    asm("mov.b64 {%0, %1}, %2;" : "=f"(r.x), "=f"(r.y) : "l"(v));
    return r;
}
__device__ __forceinline__ void ffma2(ull& acc, ull a, ull b) {
    asm("fma.rn.f32x2 %0, %1, %2, %0;" : "+l"(acc) : "l"(a), "l"(b));
}
__device__ __forceinline__ float eluf(float x) { return x > 0.f ? x : (expf(x) - 1.f); }

// ---------------- dtype detect ----------------
__global__ void k_detect(const int* __restrict__ ei32) {
    int nz = 0;
    for (int i = threadIdx.x; i < 1024; i += blockDim.x)
        if (ei32[2 * i + 1] != 0) nz = 1;
    int cnt = __syncthreads_count(nz);
    if (threadIdx.x == 0) g_is64 = (cnt == 0) ? 1 : 0;
}

// ---------------- CSR build ----------------
__global__ void k_zdeg() {
    int i = blockIdx.x * blockDim.x + threadIdx.x;
    if (i < NN) g_deg[i] = 0;
}

__global__ void k_hist(const void* __restrict__ ei) {
    int is64 = g_is64;
    int e = blockIdx.x * blockDim.x + threadIdx.x;
    if (e >= EE) return;
    int s, d;
    if (is64) {
        s = (int)((const long long*)ei)[e];
        d = (int)((const long long*)ei)[EE + e];
    } else {
        s = ((const int*)ei)[e];
        d = ((const int*)ei)[EE + e];
    }
    s = min(max(s, 0), NN - 1);
    d = min(max(d, 0), NN - 1);
    g_epack[e] = make_int2(s, d);
    atomicAdd(&g_deg[d], 1);
}

__global__ void k_scan1() {
    __shared__ int sm[256];
    int i = blockIdx.x * 256 + threadIdx.x;
    int v = (i < NN) ? g_deg[i] : 0;
    sm[threadIdx.x] = v;
    __syncthreads();
    for (int off = 1; off < 256; off <<= 1) {
        int t = (threadIdx.x >= off) ? sm[threadIdx.x - off] : 0;
        __syncthreads();
        sm[threadIdx.x] += t;
        __syncthreads();
    }
    int incl = sm[threadIdx.x];
    if (i < NN) g_rp[i] = incl - v;
    if (threadIdx.x == 255) g_btot[blockIdx.x] = incl;
}

__global__ void k_scan2() {
    __shared__ int sm[512];
    int tid = threadIdx.x;
    int v = (tid < SCAN_BLKS) ? g_btot[tid] : 0;
    sm[tid] = v;
    __syncthreads();
    for (int off = 1; off < 512; off <<= 1) {
        int t = (tid >= off) ? sm[tid - off] : 0;
        __syncthreads();
        sm[tid] += t;
        __syncthreads();
    }
    if (tid < SCAN_BLKS) g_boff[tid] = sm[tid] - v;
}

__global__ void k_scan3() {
    int i = blockIdx.x * blockDim.x + threadIdx.x;
    if (i < NN) {
        int rp = g_rp[i] + g_boff[i >> 8];
        g_rowptr[i] = rp;
        g_cursor[i] = rp;
    }
    if (i == 0) g_rowptr[NN] = EE;
}

__global__ void k_scat() {
    int e = blockIdx.x * blockDim.x + threadIdx.x;
    if (e >= EE) return;
    int2 sd = g_epack[e];
    int pos = atomicAdd(&g_cursor[sd.y], 1);
    g_csrc[pos] = sd.x;
}

// ---------------- embedding: h0 = x @ emb_w + emb_b ----------------
__global__ void __launch_bounds__(NTPB, 2) k_emb(const float* __restrict__ x,
                                                 const float* __restrict__ w,
                                                 const float* __restrict__ b) {
    __shared__ float4 sW4[IND * HIDD / 4];   // 32 KB
    __shared__ float sb[HIDD];
    int tid = threadIdx.x;
    const float4* wg = reinterpret_cast<const float4*>(w);
    for (int i = tid; i < IND * HIDD / 4; i += NTPB) sW4[i] = wg[i];
    if (tid < HIDD) sb[tid] = b[tid];
    __syncthreads();

    int jq = tid & 3;
    int n0 = blockIdx.x * 256 + (tid >> 2) * 4;
    bool av[4]; int nn[4];
#pragma unroll
    for (int i = 0; i < 4; i++) {
        int n = n0 + i;
        av[i] = (n < NN);
        nn[i] = av[i] ? n : 0;
    }

    ull acc[4][8];
#pragma unroll
    for (int i = 0; i < 4; i++)
#pragma unroll
        for (int j = 0; j < 8; j++)
            acc[i][j] = pk2(sb[jq * 16 + 2 * j], sb[jq * 16 + 2 * j + 1]);

    const char* wbase = reinterpret_cast<const char*>(sW4) + jq * 64;

    for (int k4 = 0; k4 < IND / 4; k4++) {
        float4 f[4];
#pragma unroll
        for (int i = 0; i < 4; i++)
            f[i] = reinterpret_cast<const float4*>(x + (size_t)nn[i] * IND)[k4];
#pragma unroll
        for (int q = 0; q < 4; q++) {
            ull hp[4];
            hp[0] = dup2(q == 0 ? f[0].x : q == 1 ? f[0].y : q == 2 ? f[0].z : f[0].w);
            hp[1] = dup2(q == 0 ? f[1].x : q == 1 ? f[1].y : q == 2 ? f[1].z : f[1].w);
            hp[2] = dup2(q == 0 ? f[2].x : q == 1 ? f[2].y : q == 2 ? f[2].z : f[2].w);
            hp[3] = dup2(q == 0 ? f[3].x : q == 1 ? f[3].y : q == 2 ? f[3].z : f[3].w);
            const ulonglong2* wrow =
                reinterpret_cast<const ulonglong2*>(wbase + (k4 * 4 + q) * (HIDD * 4));
#pragma unroll
            for (int j4 = 0; j4 < 4; j4++) {
                ulonglong2 wv = wrow[j4];
#pragma unroll
                for (int i = 0; i < 4; i++) {
                    ffma2(acc[i][2 * j4], hp[i], wv.x);
                    ffma2(acc[i][2 * j4 + 1], hp[i], wv.y);
                }
            }
        }
    }

#pragma unroll
    for (int i = 0; i < 4; i++) {
        if (!av[i]) continue;
        float4* o = g_h0 + (size_t)nn[i] * 16 + jq * 4;
#pragma unroll
        for (int q = 0; q < 4; q++) {
            float2 u = upk2(acc[i][2 * q]), v = upk2(acc[i][2 * q + 1]);
            o[q] = make_float4(u.x, u.y, v.x, v.y);
        }
    }
}

// ---------------- per-layer GEMM + scores + block max ----------------
__global__ void __launch_bounds__(NTPB, 2) k_gemm_s(int layer,
                                                    const float* __restrict__ W,
                                                    const float* __restrict__ avec) {
    __shared__ float4 sW4[HIDD * HIDD / 4];  // 16 KB
    __shared__ float sa[2 * HIDD];
    __shared__ float sInv;
    int tid = threadIdx.x;
    const float4* wg = reinterpret_cast<const float4*>(W);
    for (int i = tid; i < HIDD * HIDD / 4; i += NTPB) sW4[i] = wg[i];
    if (tid < 2 * HIDD) sa[tid] = avec[tid];

    if (layer) {
        float t = 0.0f;
        for (int i = tid; i < EGRID; i += NTPB) t += g_psum[i];
#pragma unroll
        for (int o = 16; o; o >>= 1) t += __shfl_xor_sync(0xffffffffu, t, o);
        __shared__ float sm[8];
        if ((tid & 31) == 0) sm[tid >> 5] = t;
        __syncthreads();
        if (tid == 0) {
            float s = 0.0f;
            for (int i = 0; i < 8; i++) s += sm[i];
            sInv = (s > 0.0f) ? (1.0f / s) : 0.0f;
        }
    }
    __syncthreads();
    float inv = layer ? sInv : 1.0f;

    int jq = tid & 3;
    int n0 = blockIdx.x * 256 + (tid >> 2) * 4;
    bool av[4]; int nn[4];
#pragma unroll
    for (int i = 0; i < 4; i++) {
        int n = n0 + i;
        av[i] = (n < NN);
        nn[i] = av[i] ? n : 0;
    }

    ull acc[4][8];
#pragma unroll
    for (int i = 0; i < 4; i++)
#pragma unroll
        for (int j = 0; j < 8; j++) acc[i][j] = 0ull;

    const float4* hb = layer ? g_h1 : g_h0;
    const char* wbase = reinterpret_cast<const char*>(sW4) + jq * 64;

    for (int k4 = 0; k4 < HIDD / 4; k4++) {
        float4 f[4];
#pragma unroll
        for (int i = 0; i < 4; i++) {
            float4 t = hb[(size_t)nn[i] * 16 + k4];
            if (layer) {
                t.x = eluf(t.x * inv); t.y = eluf(t.y * inv);
                t.z = eluf(t.z * inv); t.w = eluf(t.w * inv);
            }
            f[i] = t;
        }
#pragma unroll
        for (int q = 0; q < 4; q++) {
            ull hp[4];
            hp[0] = dup2(q == 0 ? f[0].x : q == 1 ? f[0].y : q == 2 ? f[0].z : f[0].w);
            hp[1] = dup2(q == 0 ? f[1].x : q == 1 ? f[1].y : q == 2 ? f[1].z : f[1].w);
            hp[2] = dup2(q == 0 ? f[2].x : q == 1 ? f[2].y : q == 2 ? f[2].z : f[2].w);
            hp[3] = dup2(q == 0 ? f[3].x : q == 1 ? f[3].y : q == 2 ? f[3].z : f[3].w);
            const ulonglong2* wrow =
                reinterpret_cast<const ulonglong2*>(wbase + (k4 * 4 + q) * (HIDD * 4));
#pragma unroll
            for (int j4 = 0; j4 < 4; j4++) {
                ulonglong2 wv = wrow[j4];
#pragma unroll
                for (int i = 0; i < 4; i++) {
                    ffma2(acc[i][2 * j4], hp[i], wv.x);
                    ffma2(acc[i][2 * j4 + 1], hp[i], wv.y);
                }
            }
        }
    }

    float ss[4], sd[4];
#pragma unroll
    for (int i = 0; i < 4; i++) {
        float s1 = 0.f, s2 = 0.f;
#pragma unroll
        for (int j = 0; j < 8; j++) {
            float2 v = upk2(acc[i][j]);
            s1 += v.x * sa[jq * 16 + 2 * j] + v.y * sa[jq * 16 + 2 * j + 1];
            s2 += v.x * sa[HIDD + jq * 16 + 2 * j] + v.y * sa[HIDD + jq * 16 + 2 * j + 1];
        }
        s1 += __shfl_xor_sync(0xffffffffu, s1, 1);
        s1 += __shfl_xor_sync(0xffffffffu, s1, 2);
        s2 += __shfl_xor_sync(0xffffffffu, s2, 1);
        s2 += __shfl_xor_sync(0xffffffffu, s2, 2);
        ss[i] = s1; sd[i] = s2;
    }

#pragma unroll
    for (int i = 0; i < 4; i++) {
        if (!av[i]) continue;
        if (jq == 0) { g_ssrc[nn[i]] = ss[i]; g_sdst[nn[i]] = sd[i]; }
        float4* wout = g_wh + (size_t)nn[i] * 16 + jq * 4;
#pragma unroll
        for (int q = 0; q < 4; q++) {
            float2 u = upk2(acc[i][2 * q]), v = upk2(acc[i][2 * q + 1]);
            wout[q] = make_float4(u.x, u.y, v.x, v.y);
        }
    }

    float ms = -3.4e38f, md = -3.4e38f;
#pragma unroll
    for (int i = 0; i < 4; i++) {
        if (av[i]) { ms = fmaxf(ms, ss[i]); md = fmaxf(md, sd[i]); }
    }
#pragma unroll
    for (int o = 16; o; o >>= 1) {
        ms = fmaxf(ms, __shfl_xor_sync(0xffffffffu, ms, o));
        md = fmaxf(md, __shfl_xor_sync(0xffffffffu, md, o));
    }
    __shared__ float sms[8], smd[8];
    if ((tid & 31) == 0) { sms[tid >> 5] = ms; smd[tid >> 5] = md; }
    __syncthreads();
    if (tid == 0) {
        float a = sms[0], b = smd[0];
        for (int i = 1; i < 8; i++) { a = fmaxf(a, sms[i]); b = fmaxf(b, smd[i]); }
        g_pmax_s[blockIdx.x] = a;
        g_pmax_d[blockIdx.x] = b;
    }
}

// ---------------- CSR aggregation: warp per dst, float2 lanes, 4-edge extraction ----------------
__global__ void __launch_bounds__(ETPB) k_aggr(int layer) {
    __shared__ float sB;
    {
        float a = -3.4e38f, b = -3.4e38f;
        for (int i = threadIdx.x; i < NBG; i += ETPB) {
            a = fmaxf(a, g_pmax_s[i]);
            b = fmaxf(b, g_pmax_d[i]);
        }
#pragma unroll
        for (int o = 16; o; o >>= 1) {
            a = fmaxf(a, __shfl_xor_sync(0xffffffffu, a, o));
            b = fmaxf(b, __shfl_xor_sync(0xffffffffu, b, o));
        }
        __shared__ float ra[EWPB], rb[EWPB];
        if ((threadIdx.x & 31) == 0) { ra[threadIdx.x >> 5] = a; rb[threadIdx.x >> 5] = b; }
        __syncthreads();
        if (threadIdx.x == 0) {
            float ma = ra[0], mb = rb[0];
            for (int i = 1; i < EWPB; i++) { ma = fmaxf(ma, ra[i]); mb = fmaxf(mb, rb[i]); }
            sB = ma + mb;
        }
        __syncthreads();
    }
    const float B = sB;

    int lane = threadIdx.x & 31;
    int wid = threadIdx.x >> 5;

    const float2* wh2 = reinterpret_cast<const float2*>(g_wh);   // 32 float2 per node
    float2* acc2 = reinterpret_cast<float2*>(layer ? g_hacc : g_h1);

    float psum = 0.0f;
    for (int d = blockIdx.x * EWPB + wid; d < NN; d += EWARPS) {
        int beg = g_rowptr[d];
        int end = g_rowptr[d + 1];
        float sdd = g_sdst[d];
        float2 A0 = make_float2(0.f, 0.f), A1 = A0, A2 = A0, A3 = A0;

        for (int c = beg; c < end; c += 32) {
            int e = c + lane;
            int s = 0; float p = 0.f;
            if (e < end) {
                s = g_csrc[e];
                float sc = g_ssrc[s] + sdd;
                if (sc > 0.f) p = expf(sc - B);
            }
            psum += p;

            unsigned act = __ballot_sync(0xffffffffu, p != 0.f);
            while (act) {
                int j0 = __ffs(act) - 1; act &= act - 1;
                int j1 = act ? (__ffs(act) - 1) : -1; if (j1 >= 0) act &= act - 1;
                int j2 = act ? (__ffs(act) - 1) : -1; if (j2 >= 0) act &= act - 1;
                int j3 = act ? (__ffs(act) - 1) : -1; if (j3 >= 0) act &= act - 1;

                int   s0 = __shfl_sync(0xffffffffu, s, j0);
                float p0 = __shfl_sync(0xffffffffu, p, j0);
                int   s1 = __shfl_sync(0xffffffffu, s, j1 & 31);
                float p1 = __shfl_sync(0xffffffffu, p, j1 & 31);
                int   s2 = __shfl_sync(0xffffffffu, s, j2 & 31);
                float p2 = __shfl_sync(0xffffffffu, p, j2 & 31);
                int   s3 = __shfl_sync(0xffffffffu, s, j3 & 31);
                float p3 = __shfl_sync(0xffffffffu, p, j3 & 31);

                // up to 4 independent 256B gathers in flight
                float2 x0 = wh2[(size_t)s0 * 32 + lane];
                A0.x += p0 * x0.x; A0.y += p0 * x0.y;
                if (j1 >= 0) {
                    float2 x1 = wh2[(size_t)s1 * 32 + lane];
                    A1.x += p1 * x1.x; A1.y += p1 * x1.y;
                }
                if (j2 >= 0) {
                    float2 x2 = wh2[(size_t)s2 * 32 + lane];
                    A2.x += p2 * x2.x; A2.y += p2 * x2.y;
                }
                if (j3 >= 0) {
                    float2 x3 = wh2[(size_t)s3 * 32 + lane];
                    A3.x += p3 * x3.x; A3.y += p3 * x3.y;
                }
            }
        }

        float2 R;
        R.x = (A0.x + A1.x) + (A2.x + A3.x);
        R.y = (A0.y + A1.y) + (A2.y + A3.y);
        acc2[(size_t)d * 32 + lane] = R;
    }

#pragma unroll
    for (int o = 16; o; o >>= 1) psum += __shfl_xor_sync(0xffffffffu, psum, o);
    __shared__ float sm2[EWPB];
    if (lane == 0) sm2[wid] = psum;
    __syncthreads();
    if (threadIdx.x == 0) {
        float t = 0.0f;
        for (int i = 0; i < EWPB; i++) t += sm2[i];
        g_psum[blockIdx.x] = t;
    }
}

// ---------------- output head: transform + GEMM + ELU + log_softmax ----------------
__global__ void __launch_bounds__(NTPB, 2) k_out(const float* __restrict__ W,
                                                 const float* __restrict__ b,
                                                 float* __restrict__ out) {
    __shared__ __align__(16) float sW[HIDD * NC];   // 10 KB
    __shared__ float sb[NC];
    __shared__ float sInv;
    int tid = threadIdx.x;
    for (int i = tid; i < HIDD * NC; i += NTPB) sW[i] = W[i];
    if (tid < NC) sb[tid] = b[tid];
    {
        float t = 0.0f;
        for (int i = tid; i < EGRID; i += NTPB) t += g_psum[i];
#pragma unroll
        for (int o = 16; o; o >>= 1) t += __shfl_xor_sync(0xffffffffu, t, o);
        __shared__ float sm[8];
        if ((tid & 31) == 0) sm[tid >> 5] = t;
        __syncthreads();
        if (tid == 0) {
            float s = 0.0f;
            for (int i = 0; i < 8; i++) s += sm[i];
            sInv = (s > 0.0f) ? (1.0f / s) : 0.0f;
        }
    }
    __syncthreads();
    float inv = sInv;

    int jq = tid & 3;
    int n0 = blockIdx.x * 256 + (tid >> 2) * 4;
    bool av[4]; int nn[4];
#pragma unroll
    for (int i = 0; i < 4; i++) {
        int n = n0 + i;
        av[i] = (n < NN);
        nn[i] = av[i] ? n : 0;
    }

    ull acc[4][5];
#pragma unroll
    for (int i = 0; i < 4; i++)
#pragma unroll
        for (int j = 0; j < 5; j++)
            acc[i][j] = pk2(sb[jq * 10 + 2 * j], sb[jq * 10 + 2 * j + 1]);

    const char* wbase = reinterpret_cast<const char*>(sW) + jq * 40;

    for (int k4 = 0; k4 < HIDD / 4; k4++) {
        float4 f[4];
#pragma unroll
        for (int i = 0; i < 4; i++) {
            float4 t = g_hacc[(size_t)nn[i] * 16 + k4];
            t.x = eluf(t.x * inv); t.y = eluf(t.y * inv);
            t.z = eluf(t.z * inv); t.w = eluf(t.w * inv);
            f[i] = t;
        }
#pragma unroll
        for (int q = 0; q < 4; q++) {
            ull hp[4];
            hp[0] = dup2(q == 0 ? f[0].x : q == 1 ? f[0].y : q == 2 ? f[0].z : f[0].w);
            hp[1] = dup2(q == 0 ? f[1].x : q == 1 ? f[1].y : q == 2 ? f[1].z : f[1].w);
            hp[2] = dup2(q == 0 ? f[2].x : q == 1 ? f[2].y : q == 2 ? f[2].z : f[2].w);
            hp[3] = dup2(q == 0 ? f[3].x : q == 1 ? f[3].y : q == 2 ? f[3].z : f[3].w);
            const ull* wrow = reinterpret_cast<const ull*>(wbase + (k4 * 4 + q) * (NC * 4));
#pragma unroll
            for (int j = 0; j < 5; j++) {
                ull wv = wrow[j];
#pragma unroll
                for (int i = 0; i < 4; i++) ffma2(acc[i][j], hp[i], wv);
            }
        }
    }

#pragma unroll
    for (int i = 0; i < 4; i++) {
        float v[10];
#pragma unroll
        for (int j = 0; j < 5; j++) {
            float2 u = upk2(acc[i][j]);
            v[2 * j] = u.x;
            v[2 * j + 1] = u.y;
        }
        float m = -3.4e38f;
#pragma unroll
        for (int j = 0; j < 10; j++) {
            v[j] = (v[j] > 0.f) ? v[j] : (expf(v[j]) - 1.f);
            m = fmaxf(m, v[j]);
        }
        m = fmaxf(m, __shfl_xor_sync(0xffffffffu, m, 1));
        m = fmaxf(m, __shfl_xor_sync(0xffffffffu, m, 2));

        float se = 0.f;
#pragma unroll
        for (int j = 0; j < 10; j++) se += expf(v[j] - m);
        se += __shfl_xor_sync(0xffffffffu, se, 1);
        se += __shfl_xor_sync(0xffffffffu, se, 2);
        float lse = m + logf(se);

        if (av[i]) {
            float* o = out + (size_t)nn[i] * NC + jq * 10;
#pragma unroll
            for (int j = 0; j < 10; j++) o[j] = v[j] - lse;
        }
    }
}

// ---------------- launch ----------------
extern "C" void kernel_launch(void* const* d_in, const int* in_sizes, int n_in,
                              void* d_out, int out_size) {
    const float* x      = (const float*)d_in[0];
    const void*  ei     = (const void*)d_in[1];
    const float* emb_w  = (const float*)d_in[2];
    const float* emb_b  = (const float*)d_in[3];
    const float* Ws     = (const float*)d_in[4];
    const float* attn_a = (const float*)d_in[5];
    const float* out_w  = (const float*)d_in[6];
    const float* out_b  = (const float*)d_in[7];
    float* out          = (float*)d_out;

    (void)in_sizes; (void)n_in; (void)out_size;

    const int EB = (EE + 255) / 256;
    const int NB = (NN + 255) / 256;

    k_detect<<<1, 256>>>((const int*)ei);
    k_zdeg<<<NB, 256>>>();
    k_hist<<<EB, 256>>>(ei);
    k_scan1<<<SCAN_BLKS, 256>>>();
    k_scan2<<<1, 512>>>();
    k_scan3<<<NB, 256>>>();
    k_scat<<<EB, 256>>>();

    k_emb<<<NBG, NTPB>>>(x, emb_w, emb_b);

    for (int l = 0; l < 2; l++) {
        k_gemm_s<<<NBG, NTPB>>>(l, Ws + l * HIDD * HIDD, attn_a + l * 2 * HIDD);
        k_aggr<<<EGRID, ETPB>>>(l);
    }

    k_out<<<NBG, NTPB>>>(out_w, out_b, out);
}

// round 13
// speedup vs baseline: 1.0532x; 1.0532x over previous
#include <cuda_runtime.h>
#include <cuda_fp16.h>

#define NN 100000
#define EE 1600000
#define IND 128
#define HIDD 64
#define NC 40

#define NBG 391               // ceil(NN / 256)
#define NTPB 256
#define EGRID 1184
#define ETPB 256
#define EWPB (ETPB / 32)
#define EWARPS (EGRID * EWPB)
#define SCAN_BLKS 391         // ceil(NN/256)

typedef unsigned long long ull;

// ---------------- device scratch ----------------
__device__ float4   g_h0[NN * 16];    // embedding output
__device__ float4   g_h1[NN * 16];    // layer-0 aggregate (raw)
__device__ float4   g_hacc[NN * 16];  // layer-1 aggregate (raw)
__device__ unsigned g_whh[NN * 32];   // wh rows, half2-packed (128 B/node)
__device__ float    g_ssrc[NN];
__device__ float    g_sdst[NN];
__device__ float    g_pmax_s[NBG];
__device__ float    g_pmax_d[NBG];
__device__ float    g_psum[EGRID];
__device__ int      g_is64;
// CSR
__device__ int2     g_epack[EE];
__device__ int      g_deg[NN];
__device__ int      g_rp[NN];
__device__ int      g_btot[SCAN_BLKS];
__device__ int      g_boff[SCAN_BLKS];
__device__ int      g_rowptr[NN + 1];
__device__ int      g_cursor[NN];
__device__ int      g_csrc[EE];

// ---------------- f32x2 helpers ----------------
__device__ __forceinline__ ull pk2(float a, float b) {
    ull r;
    asm("mov.b64 %0, {%1, %2};" : "=l"(r) : "f"(a), "f"(b));
    return r;
}
__device__ __forceinline__ ull dup2(float a) { return pk2(a, a); }
__device__ __forceinline__ float2 upk2(ull v) {
    float2 r;
    asm("mov.b64 {%0, %1}, %2;" : "=f"(r.x), "=f"(r.y) : "l"(v));
    return r;
}
__device__ __forceinline__ void ffma2(ull& acc, ull a, ull b) {
    asm("fma.rn.f32x2 %0, %1, %2, %0;" : "+l"(acc) : "l"(a), "l"(b));
}
__device__ __forceinline__ float eluf(float x) { return x > 0.f ? x : (expf(x) - 1.f); }

// ---------------- dtype detect + zero degrees (fused) ----------------
__global__ void k_detect_zdeg(const int* __restrict__ ei32) {
    int i = blockIdx.x * blockDim.x + threadIdx.x;
    if (i < NN) g_deg[i] = 0;
    if (blockIdx.x == 0) {
        int nz = 0;
        for (int k = threadIdx.x; k < 1024; k += blockDim.x)
            if (ei32[2 * k + 1] != 0) nz = 1;
        int cnt = __syncthreads_count(nz);
        if (threadIdx.x == 0) g_is64 = (cnt == 0) ? 1 : 0;
    }
}

// ---------------- CSR build ----------------
__global__ void k_hist(const void* __restrict__ ei) {
    int is64 = g_is64;
    int e = blockIdx.x * blockDim.x + threadIdx.x;
    if (e >= EE) return;
    int s, d;
    if (is64) {
        s = (int)((const long long*)ei)[e];
        d = (int)((const long long*)ei)[EE + e];
    } else {
        s = ((const int*)ei)[e];
        d = ((const int*)ei)[EE + e];
    }
    s = min(max(s, 0), NN - 1);
    d = min(max(d, 0), NN - 1);
    g_epack[e] = make_int2(s, d);
    atomicAdd(&g_deg[d], 1);
}

__global__ void k_scan1() {
    __shared__ int sm[256];
    int i = blockIdx.x * 256 + threadIdx.x;
    int v = (i < NN) ? g_deg[i] : 0;
    sm[threadIdx.x] = v;
    __syncthreads();
    for (int off = 1; off < 256; off <<= 1) {
        int t = (threadIdx.x >= off) ? sm[threadIdx.x - off] : 0;
        __syncthreads();
        sm[threadIdx.x] += t;
        __syncthreads();
    }
    int incl = sm[threadIdx.x];
    if (i < NN) g_rp[i] = incl - v;
    if (threadIdx.x == 255) g_btot[blockIdx.x] = incl;
}

__global__ void k_scan2() {
    __shared__ int sm[512];
    int tid = threadIdx.x;
    int v = (tid < SCAN_BLKS) ? g_btot[tid] : 0;
    sm[tid] = v;
    __syncthreads();
    for (int off = 1; off < 512; off <<= 1) {
        int t = (tid >= off) ? sm[tid - off] : 0;
        __syncthreads();
        sm[tid] += t;
        __syncthreads();
    }
    if (tid < SCAN_BLKS) g_boff[tid] = sm[tid] - v;
}

__global__ void k_scan3() {
    int i = blockIdx.x * blockDim.x + threadIdx.x;
    if (i < NN) {
        int rp = g_rp[i] + g_boff[i >> 8];
        g_rowptr[i] = rp;
        g_cursor[i] = rp;
    }
    if (i == 0) g_rowptr[NN] = EE;
}

__global__ void k_scat() {
    int e = blockIdx.x * blockDim.x + threadIdx.x;
    if (e >= EE) return;
    int2 sd = g_epack[e];
    int pos = atomicAdd(&g_cursor[sd.y], 1);
    g_csrc[pos] = sd.x;
}

// ---------------- embedding: h0 = x @ emb_w + emb_b ----------------
__global__ void __launch_bounds__(NTPB, 2) k_emb(const float* __restrict__ x,
                                                 const float* __restrict__ w,
                                                 const float* __restrict__ b) {
    __shared__ float4 sW4[IND * HIDD / 4];   // 32 KB
    __shared__ float sb[HIDD];
    int tid = threadIdx.x;
    const float4* wg = reinterpret_cast<const float4*>(w);
    for (int i = tid; i < IND * HIDD / 4; i += NTPB) sW4[i] = wg[i];
    if (tid < HIDD) sb[tid] = b[tid];
    __syncthreads();

    int jq = tid & 3;
    int n0 = blockIdx.x * 256 + (tid >> 2) * 4;
    bool av[4]; int nn[4];
#pragma unroll
    for (int i = 0; i < 4; i++) {
        int n = n0 + i;
        av[i] = (n < NN);
        nn[i] = av[i] ? n : 0;
    }

    ull acc[4][8];
#pragma unroll
    for (int i = 0; i < 4; i++)
#pragma unroll
        for (int j = 0; j < 8; j++)
            acc[i][j] = pk2(sb[jq * 16 + 2 * j], sb[jq * 16 + 2 * j + 1]);

    const char* wbase = reinterpret_cast<const char*>(sW4) + jq * 64;

    for (int k4 = 0; k4 < IND / 4; k4++) {
        float4 f[4];
#pragma unroll
        for (int i = 0; i < 4; i++)
            f[i] = reinterpret_cast<const float4*>(x + (size_t)nn[i] * IND)[k4];
#pragma unroll
        for (int q = 0; q < 4; q++) {
            ull hp[4];
            hp[0] = dup2(q == 0 ? f[0].x : q == 1 ? f[0].y : q == 2 ? f[0].z : f[0].w);
            hp[1] = dup2(q == 0 ? f[1].x : q == 1 ? f[1].y : q == 2 ? f[1].z : f[1].w);
            hp[2] = dup2(q == 0 ? f[2].x : q == 1 ? f[2].y : q == 2 ? f[2].z : f[2].w);
            hp[3] = dup2(q == 0 ? f[3].x : q == 1 ? f[3].y : q == 2 ? f[3].z : f[3].w);
            const ulonglong2* wrow =
                reinterpret_cast<const ulonglong2*>(wbase + (k4 * 4 + q) * (HIDD * 4));
#pragma unroll
            for (int j4 = 0; j4 < 4; j4++) {
                ulonglong2 wv = wrow[j4];
#pragma unroll
                for (int i = 0; i < 4; i++) {
                    ffma2(acc[i][2 * j4], hp[i], wv.x);
                    ffma2(acc[i][2 * j4 + 1], hp[i], wv.y);
                }
            }
        }
    }

#pragma unroll
    for (int i = 0; i < 4; i++) {
        if (!av[i]) continue;
        float4* o = g_h0 + (size_t)nn[i] * 16 + jq * 4;
#pragma unroll
        for (int q = 0; q < 4; q++) {
            float2 u = upk2(acc[i][2 * q]), v = upk2(acc[i][2 * q + 1]);
            o[q] = make_float4(u.x, u.y, v.x, v.y);
        }
    }
}

// ---------------- per-layer GEMM + scores + block max; wh stored fp16 ----------------
__global__ void __launch_bounds__(NTPB, 2) k_gemm_s(int layer,
                                                    const float* __restrict__ W,
                                                    const float* __restrict__ avec) {
    __shared__ float4 sW4[HIDD * HIDD / 4];  // 16 KB
    __shared__ float sa[2 * HIDD];
    __shared__ float sInv;
    int tid = threadIdx.x;
    const float4* wg = reinterpret_cast<const float4*>(W);
    for (int i = tid; i < HIDD * HIDD / 4; i += NTPB) sW4[i] = wg[i];
    if (tid < 2 * HIDD) sa[tid] = avec[tid];

    if (layer) {
        float t = 0.0f;
        for (int i = tid; i < EGRID; i += NTPB) t += g_psum[i];
#pragma unroll
        for (int o = 16; o; o >>= 1) t += __shfl_xor_sync(0xffffffffu, t, o);
        __shared__ float sm[8];
        if ((tid & 31) == 0) sm[tid >> 5] = t;
        __syncthreads();
        if (tid == 0) {
            float s = 0.0f;
            for (int i = 0; i < 8; i++) s += sm[i];
            sInv = (s > 0.0f) ? (1.0f / s) : 0.0f;
        }
    }
    __syncthreads();
    float inv = layer ? sInv : 1.0f;

    int jq = tid & 3;
    int n0 = blockIdx.x * 256 + (tid >> 2) * 4;
    bool av[4]; int nn[4];
#pragma unroll
    for (int i = 0; i < 4; i++) {
        int n = n0 + i;
        av[i] = (n < NN);
        nn[i] = av[i] ? n : 0;
    }

    ull acc[4][8];
#pragma unroll
    for (int i = 0; i < 4; i++)
#pragma unroll
        for (int j = 0; j < 8; j++) acc[i][j] = 0ull;

    const float4* hb = layer ? g_h1 : g_h0;
    const char* wbase = reinterpret_cast<const char*>(sW4) + jq * 64;

    for (int k4 = 0; k4 < HIDD / 4; k4++) {
        float4 f[4];
#pragma unroll
        for (int i = 0; i < 4; i++) {
            float4 t = hb[(size_t)nn[i] * 16 + k4];
            if (layer) {
                t.x = eluf(t.x * inv); t.y = eluf(t.y * inv);
                t.z = eluf(t.z * inv); t.w = eluf(t.w * inv);
            }
            f[i] = t;
        }
#pragma unroll
        for (int q = 0; q < 4; q++) {
            ull hp[4];
            hp[0] = dup2(q == 0 ? f[0].x : q == 1 ? f[0].y : q == 2 ? f[0].z : f[0].w);
            hp[1] = dup2(q == 0 ? f[1].x : q == 1 ? f[1].y : q == 2 ? f[1].z : f[1].w);
            hp[2] = dup2(q == 0 ? f[2].x : q == 1 ? f[2].y : q == 2 ? f[2].z : f[2].w);
            hp[3] = dup2(q == 0 ? f[3].x : q == 1 ? f[3].y : q == 2 ? f[3].z : f[3].w);
            const ulonglong2* wrow =
                reinterpret_cast<const ulonglong2*>(wbase + (k4 * 4 + q) * (HIDD * 4));
#pragma unroll
            for (int j4 = 0; j4 < 4; j4++) {
                ulonglong2 wv = wrow[j4];
#pragma unroll
                for (int i = 0; i < 4; i++) {
                    ffma2(acc[i][2 * j4], hp[i], wv.x);
                    ffma2(acc[i][2 * j4 + 1], hp[i], wv.y);
                }
            }
        }
    }

    float ss[4], sd[4];
#pragma unroll
    for (int i = 0; i < 4; i++) {
        float s1 = 0.f, s2 = 0.f;
#pragma unroll
        for (int j = 0; j < 8; j++) {
            float2 v = upk2(acc[i][j]);
            s1 += v.x * sa[jq * 16 + 2 * j] + v.y * sa[jq * 16 + 2 * j + 1];
            s2 += v.x * sa[HIDD + jq * 16 + 2 * j] + v.y * sa[HIDD + jq * 16 + 2 * j + 1];
        }
        s1 += __shfl_xor_sync(0xffffffffu, s1, 1);
        s1 += __shfl_xor_sync(0xffffffffu, s1, 2);
        s2 += __shfl_xor_sync(0xffffffffu, s2, 1);
        s2 += __shfl_xor_sync(0xffffffffu, s2, 2);
        ss[i] = s1; sd[i] = s2;
    }

#pragma unroll
    for (int i = 0; i < 4; i++) {
        if (!av[i]) continue;
        if (jq == 0) { g_ssrc[nn[i]] = ss[i]; g_sdst[nn[i]] = sd[i]; }
        // write fp16-packed wh row segment (8 half2 = 32 B)
        unsigned* wo = g_whh + (size_t)nn[i] * 32 + jq * 8;
#pragma unroll
        for (int j = 0; j < 8; j++) {
            float2 v = upk2(acc[i][j]);
            __half2 hh = __float22half2_rn(v);
            wo[j] = *reinterpret_cast<unsigned*>(&hh);
        }
    }

    float ms = -3.4e38f, md = -3.4e38f;
#pragma unroll
    for (int i = 0; i < 4; i++) {
        if (av[i]) { ms = fmaxf(ms, ss[i]); md = fmaxf(md, sd[i]); }
    }
#pragma unroll
    for (int o = 16; o; o >>= 1) {
        ms = fmaxf(ms, __shfl_xor_sync(0xffffffffu, ms, o));
        md = fmaxf(md, __shfl_xor_sync(0xffffffffu, md, o));
    }
    __shared__ float sms[8], smd[8];
    if ((tid & 31) == 0) { sms[tid >> 5] = ms; smd[tid >> 5] = md; }
    __syncthreads();
    if (tid == 0) {
        float a = sms[0], b = smd[0];
        for (int i = 1; i < 8; i++) { a = fmaxf(a, sms[i]); b = fmaxf(b, smd[i]); }
        g_pmax_s[blockIdx.x] = a;
        g_pmax_d[blockIdx.x] = b;
    }
}

// ---------------- CSR aggregation: warp per dst, fp16 gather (r11 loop shape) ----------------
__global__ void __launch_bounds__(ETPB) k_aggr(int layer) {
    __shared__ float sB;
    {
        float a = -3.4e38f, b = -3.4e38f;
        for (int i = threadIdx.x; i < NBG; i += ETPB) {
            a = fmaxf(a, g_pmax_s[i]);
            b = fmaxf(b, g_pmax_d[i]);
        }
#pragma unroll
        for (int o = 16; o; o >>= 1) {
            a = fmaxf(a, __shfl_xor_sync(0xffffffffu, a, o));
            b = fmaxf(b, __shfl_xor_sync(0xffffffffu, b, o));
        }
        __shared__ float ra[EWPB], rb[EWPB];
        if ((threadIdx.x & 31) == 0) { ra[threadIdx.x >> 5] = a; rb[threadIdx.x >> 5] = b; }
        __syncthreads();
        if (threadIdx.x == 0) {
            float ma = ra[0], mb = rb[0];
            for (int i = 1; i < EWPB; i++) { ma = fmaxf(ma, ra[i]); mb = fmaxf(mb, rb[i]); }
            sB = ma + mb;
        }
        __syncthreads();
    }
    const float B = sB;

    int lane = threadIdx.x & 31;
    int wid = threadIdx.x >> 5;

    float2* acc2 = reinterpret_cast<float2*>(layer ? g_hacc : g_h1);

    float psum = 0.0f;
    for (int d = blockIdx.x * EWPB + wid; d < NN; d += EWARPS) {
        int beg = g_rowptr[d];
        int end = g_rowptr[d + 1];
        float sdd = g_sdst[d];
        float2 A0 = make_float2(0.f, 0.f), A1 = A0;

        for (int c = beg; c < end; c += 32) {
            int e = c + lane;
            int s = 0; float p = 0.f;
            if (e < end) {
                s = g_csrc[e];
                float sc = g_ssrc[s] + sdd;
                if (sc > 0.f) p = expf(sc - B);
            }
            psum += p;

            unsigned act = __ballot_sync(0xffffffffu, p != 0.f);
            while (act) {
                int j0 = __ffs(act) - 1; act &= act - 1;
                int s0 = __shfl_sync(0xffffffffu, s, j0);
                float p0 = __shfl_sync(0xffffffffu, p, j0);
                if (act) {
                    int j1 = __ffs(act) - 1; act &= act - 1;
                    int s1 = __shfl_sync(0xffffffffu, s, j1);
                    float p1 = __shfl_sync(0xffffffffu, p, j1);
                    unsigned u0 = g_whh[(size_t)s0 * 32 + lane];
                    unsigned u1 = g_whh[(size_t)s1 * 32 + lane];
                    float2 x0 = __half22float2(*reinterpret_cast<__half2*>(&u0));
                    float2 x1 = __half22float2(*reinterpret_cast<__half2*>(&u1));
                    A0.x += p0 * x0.x; A0.y += p0 * x0.y;
                    A1.x += p1 * x1.x; A1.y += p1 * x1.y;
                } else {
                    unsigned u0 = g_whh[(size_t)s0 * 32 + lane];
                    float2 x0 = __half22float2(*reinterpret_cast<__half2*>(&u0));
                    A0.x += p0 * x0.x; A0.y += p0 * x0.y;
                }
            }
        }

        float2 R;
        R.x = A0.x + A1.x;
        R.y = A0.y + A1.y;
        acc2[(size_t)d * 32 + lane] = R;
    }

#pragma unroll
    for (int o = 16; o; o >>= 1) psum += __shfl_xor_sync(0xffffffffu, psum, o);
    __shared__ float sm2[EWPB];
    if (lane == 0) sm2[wid] = psum;
    __syncthreads();
    if (threadIdx.x == 0) {
        float t = 0.0f;
        for (int i = 0; i < EWPB; i++) t += sm2[i];
        g_psum[blockIdx.x] = t;
    }
}

// ---------------- output head: transform + GEMM + ELU + log_softmax ----------------
__global__ void __launch_bounds__(NTPB, 2) k_out(const float* __restrict__ W,
                                                 const float* __restrict__ b,
                                                 float* __restrict__ out) {
    __shared__ __align__(16) float sW[HIDD * NC];   // 10 KB
    __shared__ float sb[NC];
    __shared__ float sInv;
    int tid = threadIdx.x;
    for (int i = tid; i < HIDD * NC; i += NTPB) sW[i] = W[i];
    if (tid < NC) sb[tid] = b[tid];
    {
        float t = 0.0f;
        for (int i = tid; i < EGRID; i += NTPB) t += g_psum[i];
#pragma unroll
        for (int o = 16; o; o >>= 1) t += __shfl_xor_sync(0xffffffffu, t, o);
        __shared__ float sm[8];
        if ((tid & 31) == 0) sm[tid >> 5] = t;
        __syncthreads();
        if (tid == 0) {
            float s = 0.0f;
            for (int i = 0; i < 8; i++) s += sm[i];
            sInv = (s > 0.0f) ? (1.0f / s) : 0.0f;
        }
    }
    __syncthreads();
    float inv = sInv;

    int jq = tid & 3;
    int n0 = blockIdx.x * 256 + (tid >> 2) * 4;
    bool av[4]; int nn[4];
#pragma unroll
    for (int i = 0; i < 4; i++) {
        int n = n0 + i;
        av[i] = (n < NN);
        nn[i] = av[i] ? n : 0;
    }

    ull acc[4][5];
#pragma unroll
    for (int i = 0; i < 4; i++)
#pragma unroll
        for (int j = 0; j < 5; j++)
            acc[i][j] = pk2(sb[jq * 10 + 2 * j], sb[jq * 10 + 2 * j + 1]);

    const char* wbase = reinterpret_cast<const char*>(sW) + jq * 40;

    for (int k4 = 0; k4 < HIDD / 4; k4++) {
        float4 f[4];
#pragma unroll
        for (int i = 0; i < 4; i++) {
            float4 t = g_hacc[(size_t)nn[i] * 16 + k4];
            t.x = eluf(t.x * inv); t.y = eluf(t.y * inv);
            t.z = eluf(t.z * inv); t.w = eluf(t.w * inv);
            f[i] = t;
        }
#pragma unroll
        for (int q = 0; q < 4; q++) {
            ull hp[4];
            hp[0] = dup2(q == 0 ? f[0].x : q == 1 ? f[0].y : q == 2 ? f[0].z : f[0].w);
            hp[1] = dup2(q == 0 ? f[1].x : q == 1 ? f[1].y : q == 2 ? f[1].z : f[1].w);
            hp[2] = dup2(q == 0 ? f[2].x : q == 1 ? f[2].y : q == 2 ? f[2].z : f[2].w);
            hp[3] = dup2(q == 0 ? f[3].x : q == 1 ? f[3].y : q == 2 ? f[3].z : f[3].w);
            const ull* wrow = reinterpret_cast<const ull*>(wbase + (k4 * 4 + q) * (NC * 4));
#pragma unroll
            for (int j = 0; j < 5; j++) {
                ull wv = wrow[j];
#pragma unroll
                for (int i = 0; i < 4; i++) ffma2(acc[i][j], hp[i], wv);
            }
        }
    }

#pragma unroll
    for (int i = 0; i < 4; i++) {
        float v[10];
#pragma unroll
        for (int j = 0; j < 5; j++) {
            float2 u = upk2(acc[i][j]);
            v[2 * j] = u.x;
            v[2 * j + 1] = u.y;
        }
        float m = -3.4e38f;
#pragma unroll
        for (int j = 0; j < 10; j++) {
            v[j] = (v[j] > 0.f) ? v[j] : (expf(v[j]) - 1.f);
            m = fmaxf(m, v[j]);
        }
        m = fmaxf(m, __shfl_xor_sync(0xffffffffu, m, 1));
        m = fmaxf(m, __shfl_xor_sync(0xffffffffu, m, 2));

        float se = 0.f;
#pragma unroll
        for (int j = 0; j < 10; j++) se += expf(v[j] - m);
        se += __shfl_xor_sync(0xffffffffu, se, 1);
        se += __shfl_xor_sync(0xffffffffu, se, 2);
        float lse = m + logf(se);

        if (av[i]) {
            float* o = out + (size_t)nn[i] * NC + jq * 10;
#pragma unroll
            for (int j = 0; j < 10; j++) o[j] = v[j] - lse;
        }
    }
}

// ---------------- launch ----------------
extern "C" void kernel_launch(void* const* d_in, const int* in_sizes, int n_in,
                              void* d_out, int out_size) {
    const float* x      = (const float*)d_in[0];
    const void*  ei     = (const void*)d_in[1];
    const float* emb_w  = (const float*)d_in[2];
    const float* emb_b  = (const float*)d_in[3];
    const float* Ws     = (const float*)d_in[4];
    const float* attn_a = (const float*)d_in[5];
    const float* out_w  = (const float*)d_in[6];
    const float* out_b  = (const float*)d_in[7];
    float* out          = (float*)d_out;

    (void)in_sizes; (void)n_in; (void)out_size;

    const int EB = (EE + 255) / 256;
    const int NB = (NN + 255) / 256;

    k_detect_zdeg<<<NB, 256>>>((const int*)ei);
    k_hist<<<EB, 256>>>(ei);
    k_scan1<<<SCAN_BLKS, 256>>>();
    k_scan2<<<1, 512>>>();
    k_scan3<<<NB, 256>>>();
    k_scat<<<EB, 256>>>();

    k_emb<<<NBG, NTPB>>>(x, emb_w, emb_b);

    for (int l = 0; l < 2; l++) {
        k_gemm_s<<<NBG, NTPB>>>(l, Ws + l * HIDD * HIDD, attn_a + l * 2 * HIDD);
        k_aggr<<<EGRID, ETPB>>>(l);
    }

    k_out<<<NBG, NTPB>>>(out_w, out_b, out);
}

// round 14
// speedup vs baseline: 1.2103x; 1.1492x over previous
#include <cuda_runtime.h>
#include <cuda_fp16.h>

#define NN 100000
#define EE 1600000
#define IND 128
#define HIDD 64
#define NC 40

#define NBG 391               // ceil(NN / 256)
#define NTPB 256
#define EGRID 1184
#define ETPB 256
#define EWPB (ETPB / 32)
#define EWARPS (EGRID * EWPB)
#define SCAN_BLKS 391

typedef unsigned long long ull;

// ---------------- device scratch ----------------
__device__ float4   g_h0[NN * 16];
__device__ float4   g_h1[NN * 16];
__device__ float4   g_hacc[NN * 16];
__device__ unsigned g_whh[NN * 32];   // wh rows, half2-packed
__device__ float    g_ssrc[NN];
__device__ float    g_sdst[NN];
__device__ float    g_pmax_s[NBG];
__device__ float    g_pmax_d[NBG];
__device__ float    g_psum[EGRID];
__device__ int      g_is64;
__device__ int2     g_epack[EE];
__device__ int      g_deg[NN];
__device__ int      g_rp[NN];
__device__ int      g_btot[SCAN_BLKS];
__device__ int      g_boff[SCAN_BLKS];
__device__ int      g_rowptr[NN + 1];
__device__ int      g_cursor[NN];
__device__ int      g_csrc[EE];

// ---------------- helpers ----------------
__device__ __forceinline__ ull pk2(float a, float b) {
    ull r;
    asm("mov.b64 %0, {%1, %2};" : "=l"(r) : "f"(a), "f"(b));
    return r;
}
__device__ __forceinline__ ull dup2(float a) { return pk2(a, a); }
__device__ __forceinline__ float2 upk2(ull v) {
    float2 r;
    asm("mov.b64 {%0, %1}, %2;" : "=f"(r.x), "=f"(r.y) : "l"(v));
    return r;
}
__device__ __forceinline__ void ffma2(ull& acc, ull a, ull b) {
    asm("fma.rn.f32x2 %0, %1, %2, %0;" : "+l"(acc) : "l"(a), "l"(b));
}
__device__ __forceinline__ float eluf(float x) { return x > 0.f ? x : (expf(x) - 1.f); }

__device__ __forceinline__ void mma16816(float* c, const unsigned* a, unsigned b0, unsigned b1) {
    asm volatile(
        "mma.sync.aligned.m16n8k16.row.col.f32.f16.f16.f32 "
        "{%0,%1,%2,%3}, {%4,%5,%6,%7}, {%8,%9}, {%0,%1,%2,%3};"
        : "+f"(c[0]), "+f"(c[1]), "+f"(c[2]), "+f"(c[3])
        : "r"(a[0]), "r"(a[1]), "r"(a[2]), "r"(a[3]), "r"(b0), "r"(b1));
}

// ---------------- dtype detect + zero degrees ----------------
__global__ void k_detect_zdeg(const int* __restrict__ ei32) {
    int i = blockIdx.x * blockDim.x + threadIdx.x;
    if (i < NN) g_deg[i] = 0;
    if (blockIdx.x == 0) {
        int nz = 0;
        for (int k = threadIdx.x; k < 1024; k += blockDim.x)
            if (ei32[2 * k + 1] != 0) nz = 1;
        int cnt = __syncthreads_count(nz);
        if (threadIdx.x == 0) g_is64 = (cnt == 0) ? 1 : 0;
    }
}

// ---------------- CSR build ----------------
__global__ void k_hist(const void* __restrict__ ei) {
    int is64 = g_is64;
    int e = blockIdx.x * blockDim.x + threadIdx.x;
    if (e >= EE) return;
    int s, d;
    if (is64) {
        s = (int)((const long long*)ei)[e];
        d = (int)((const long long*)ei)[EE + e];
    } else {
        s = ((const int*)ei)[e];
        d = ((const int*)ei)[EE + e];
    }
    s = min(max(s, 0), NN - 1);
    d = min(max(d, 0), NN - 1);
    g_epack[e] = make_int2(s, d);
    atomicAdd(&g_deg[d], 1);
}

__global__ void k_scan1() {
    __shared__ int sm[256];
    int i = blockIdx.x * 256 + threadIdx.x;
    int v = (i < NN) ? g_deg[i] : 0;
    sm[threadIdx.x] = v;
    __syncthreads();
    for (int off = 1; off < 256; off <<= 1) {
        int t = (threadIdx.x >= off) ? sm[threadIdx.x - off] : 0;
        __syncthreads();
        sm[threadIdx.x] += t;
        __syncthreads();
    }
    int incl = sm[threadIdx.x];
    if (i < NN) g_rp[i] = incl - v;
    if (threadIdx.x == 255) g_btot[blockIdx.x] = incl;
}

__global__ void k_scan2() {
    __shared__ int sm[512];
    int tid = threadIdx.x;
    int v = (tid < SCAN_BLKS) ? g_btot[tid] : 0;
    sm[tid] = v;
    __syncthreads();
    for (int off = 1; off < 512; off <<= 1) {
        int t = (tid >= off) ? sm[tid - off] : 0;
        __syncthreads();
        sm[tid] += t;
        __syncthreads();
    }
    if (tid < SCAN_BLKS) g_boff[tid] = sm[tid] - v;
}

__global__ void k_scan3() {
    int i = blockIdx.x * blockDim.x + threadIdx.x;
    if (i < NN) {
        int rp = g_rp[i] + g_boff[i >> 8];
        g_rowptr[i] = rp;
        g_cursor[i] = rp;
    }
    if (i == 0) g_rowptr[NN] = EE;
}

__global__ void k_scat() {
    int e = blockIdx.x * blockDim.x + threadIdx.x;
    if (e >= EE) return;
    int2 sd = g_epack[e];
    int pos = atomicAdd(&g_cursor[sd.y], 1);
    g_csrc[pos] = sd.x;
}

// ---------------- embedding (unchanged f32x2 path) ----------------
__global__ void __launch_bounds__(NTPB, 2) k_emb(const float* __restrict__ x,
                                                 const float* __restrict__ w,
                                                 const float* __restrict__ b) {
    __shared__ float4 sW4[IND * HIDD / 4];
    __shared__ float sb[HIDD];
    int tid = threadIdx.x;
    const float4* wg = reinterpret_cast<const float4*>(w);
    for (int i = tid; i < IND * HIDD / 4; i += NTPB) sW4[i] = wg[i];
    if (tid < HIDD) sb[tid] = b[tid];
    __syncthreads();

    int jq = tid & 3;
    int n0 = blockIdx.x * 256 + (tid >> 2) * 4;
    bool av[4]; int nn[4];
#pragma unroll
    for (int i = 0; i < 4; i++) {
        int n = n0 + i;
        av[i] = (n < NN);
        nn[i] = av[i] ? n : 0;
    }

    ull acc[4][8];
#pragma unroll
    for (int i = 0; i < 4; i++)
#pragma unroll
        for (int j = 0; j < 8; j++)
            acc[i][j] = pk2(sb[jq * 16 + 2 * j], sb[jq * 16 + 2 * j + 1]);

    const char* wbase = reinterpret_cast<const char*>(sW4) + jq * 64;

    for (int k4 = 0; k4 < IND / 4; k4++) {
        float4 f[4];
#pragma unroll
        for (int i = 0; i < 4; i++)
            f[i] = reinterpret_cast<const float4*>(x + (size_t)nn[i] * IND)[k4];
#pragma unroll
        for (int q = 0; q < 4; q++) {
            ull hp[4];
            hp[0] = dup2(q == 0 ? f[0].x : q == 1 ? f[0].y : q == 2 ? f[0].z : f[0].w);
            hp[1] = dup2(q == 0 ? f[1].x : q == 1 ? f[1].y : q == 2 ? f[1].z : f[1].w);
            hp[2] = dup2(q == 0 ? f[2].x : q == 1 ? f[2].y : q == 2 ? f[2].z : f[2].w);
            hp[3] = dup2(q == 0 ? f[3].x : q == 1 ? f[3].y : q == 2 ? f[3].z : f[3].w);
            const ulonglong2* wrow =
                reinterpret_cast<const ulonglong2*>(wbase + (k4 * 4 + q) * (HIDD * 4));
#pragma unroll
            for (int j4 = 0; j4 < 4; j4++) {
                ulonglong2 wv = wrow[j4];
#pragma unroll
                for (int i = 0; i < 4; i++) {
                    ffma2(acc[i][2 * j4], hp[i], wv.x);
                    ffma2(acc[i][2 * j4 + 1], hp[i], wv.y);
                }
            }
        }
    }

#pragma unroll
    for (int i = 0; i < 4; i++) {
        if (!av[i]) continue;
        float4* o = g_h0 + (size_t)nn[i] * 16 + jq * 4;
#pragma unroll
        for (int q = 0; q < 4; q++) {
            float2 u = upk2(acc[i][2 * q]), v = upk2(acc[i][2 * q + 1]);
            o[q] = make_float4(u.x, u.y, v.x, v.y);
        }
    }
}

// ---------------- per-layer GEMM via tensor cores (mma.sync m16n8k16) ----------------
// 256 threads = 8 warps; CTA covers 256 nodes. Warp w owns rows [w*32, w*32+32).
#define HSTRIDE 72
__global__ void __launch_bounds__(NTPB, 2) k_gemm_s(int layer,
                                                    const float* __restrict__ W,
                                                    const float* __restrict__ avec) {
    __shared__ __half sH[256 * HSTRIDE];   // 36864 B
    __shared__ __half sWt[64 * HSTRIDE];   // 9216 B, n-major: sWt[n*72 + k]
    __shared__ float sa[2 * HIDD];
    __shared__ float sInv;
    int tid = threadIdx.x;

    if (tid < 2 * HIDD) sa[tid] = avec[tid];

    if (layer) {
        float t = 0.0f;
        for (int i = tid; i < EGRID; i += NTPB) t += g_psum[i];
#pragma unroll
        for (int o = 16; o; o >>= 1) t += __shfl_xor_sync(0xffffffffu, t, o);
        __shared__ float smr[8];
        if ((tid & 31) == 0) smr[tid >> 5] = t;
        __syncthreads();
        if (tid == 0) {
            float s = 0.0f;
            for (int i = 0; i < 8; i++) s += smr[i];
            sInv = (s > 0.0f) ? (1.0f / s) : 0.0f;
        }
        __syncthreads();
    }
    float inv = layer ? sInv : 1.0f;

    // stage W transposed to fp16 (n-major rows of K)
    for (int i = tid; i < HIDD * HIDD; i += NTPB) {
        int k = i >> 6, n = i & 63;
        sWt[n * HSTRIDE + k] = __float2half(W[i]);
    }

    // stage h tile: thread tid -> row tid (node)
    {
        int node = blockIdx.x * 256 + tid;
        int nc = (node < NN) ? node : 0;
        const float4* hr = (layer ? g_h1 : g_h0) + (size_t)nc * 16;
        __half2* dst = reinterpret_cast<__half2*>(sH + tid * HSTRIDE);
#pragma unroll
        for (int k4 = 0; k4 < 16; k4++) {
            float4 v = hr[k4];
            if (layer) {
                v.x = eluf(v.x * inv); v.y = eluf(v.y * inv);
                v.z = eluf(v.z * inv); v.w = eluf(v.w * inv);
            }
            dst[2 * k4]     = __floats2half2_rn(v.x, v.y);
            dst[2 * k4 + 1] = __floats2half2_rn(v.z, v.w);
        }
    }
    __syncthreads();

    int w = tid >> 5;
    int lane = tid & 31;
    int grp = lane >> 2;   // 0..7
    int qid = lane & 3;    // 0..3

    float c[2][8][4];
#pragma unroll
    for (int mt = 0; mt < 2; mt++)
#pragma unroll
        for (int nt = 0; nt < 8; nt++)
#pragma unroll
            for (int q = 0; q < 4; q++) c[mt][nt][q] = 0.f;

#pragma unroll
    for (int kc = 0; kc < 4; kc++) {
        int k0 = kc * 16 + 2 * qid;
        unsigned a[2][4];
#pragma unroll
        for (int mt = 0; mt < 2; mt++) {
            const __half* base = sH + (w * 32 + mt * 16 + grp) * HSTRIDE;
            a[mt][0] = *reinterpret_cast<const unsigned*>(base + k0);
            a[mt][1] = *reinterpret_cast<const unsigned*>(base + 8 * HSTRIDE + k0);
            a[mt][2] = *reinterpret_cast<const unsigned*>(base + k0 + 8);
            a[mt][3] = *reinterpret_cast<const unsigned*>(base + 8 * HSTRIDE + k0 + 8);
        }
#pragma unroll
        for (int nt = 0; nt < 8; nt++) {
            const __half* bb = sWt + (nt * 8 + grp) * HSTRIDE + k0;
            unsigned b0 = *reinterpret_cast<const unsigned*>(bb);
            unsigned b1 = *reinterpret_cast<const unsigned*>(bb + 8);
            mma16816(c[0][nt], a[0], b0, b1);
            mma16816(c[1][nt], a[1], b0, b1);
        }
    }

    // epilogue: scores + wh store + block max
    float rmax_s = -3.4e38f, rmax_d = -3.4e38f;
#pragma unroll
    for (int mt = 0; mt < 2; mt++) {
        float ss0 = 0.f, ss1 = 0.f, sd0 = 0.f, sd1 = 0.f;
#pragma unroll
        for (int nt = 0; nt < 8; nt++) {
            int col = nt * 8 + 2 * qid;
            float as0 = sa[col], as1 = sa[col + 1];
            float ad0 = sa[HIDD + col], ad1 = sa[HIDD + col + 1];
            ss0 += c[mt][nt][0] * as0 + c[mt][nt][1] * as1;
            sd0 += c[mt][nt][0] * ad0 + c[mt][nt][1] * ad1;
            ss1 += c[mt][nt][2] * as0 + c[mt][nt][3] * as1;
            sd1 += c[mt][nt][2] * ad0 + c[mt][nt][3] * ad1;
        }
        ss0 += __shfl_xor_sync(0xffffffffu, ss0, 1);
        ss0 += __shfl_xor_sync(0xffffffffu, ss0, 2);
        sd0 += __shfl_xor_sync(0xffffffffu, sd0, 1);
        sd0 += __shfl_xor_sync(0xffffffffu, sd0, 2);
        ss1 += __shfl_xor_sync(0xffffffffu, ss1, 1);
        ss1 += __shfl_xor_sync(0xffffffffu, ss1, 2);
        sd1 += __shfl_xor_sync(0xffffffffu, sd1, 1);
        sd1 += __shfl_xor_sync(0xffffffffu, sd1, 2);

        int row0 = w * 32 + mt * 16 + grp;
        int row1 = row0 + 8;
        int node0 = blockIdx.x * 256 + row0;
        int node1 = blockIdx.x * 256 + row1;

        if (qid == 0) {
            if (node0 < NN) { g_ssrc[node0] = ss0; g_sdst[node0] = sd0; }
            if (node1 < NN) { g_ssrc[node1] = ss1; g_sdst[node1] = sd1; }
        }
        if (node0 < NN) { rmax_s = fmaxf(rmax_s, ss0); rmax_d = fmaxf(rmax_d, sd0); }
        if (node1 < NN) { rmax_s = fmaxf(rmax_s, ss1); rmax_d = fmaxf(rmax_d, sd1); }

        // wh fp16 store from fragments
#pragma unroll
        for (int nt = 0; nt < 8; nt++) {
            int pidx = qid + nt * 4;
            if (node0 < NN) {
                __half2 h0 = __floats2half2_rn(c[mt][nt][0], c[mt][nt][1]);
                g_whh[(size_t)node0 * 32 + pidx] = *reinterpret_cast<unsigned*>(&h0);
            }
            if (node1 < NN) {
                __half2 h1 = __floats2half2_rn(c[mt][nt][2], c[mt][nt][3]);
                g_whh[(size_t)node1 * 32 + pidx] = *reinterpret_cast<unsigned*>(&h1);
            }
        }
    }

    // block max partials
#pragma unroll
    for (int o = 16; o; o >>= 1) {
        rmax_s = fmaxf(rmax_s, __shfl_xor_sync(0xffffffffu, rmax_s, o));
        rmax_d = fmaxf(rmax_d, __shfl_xor_sync(0xffffffffu, rmax_d, o));
    }
    __shared__ float sms[8], smd[8];
    if (lane == 0) { sms[w] = rmax_s; smd[w] = rmax_d; }
    __syncthreads();
    if (tid == 0) {
        float a = sms[0], b = smd[0];
        for (int i = 1; i < 8; i++) { a = fmaxf(a, sms[i]); b = fmaxf(b, smd[i]); }
        g_pmax_s[blockIdx.x] = a;
        g_pmax_d[blockIdx.x] = b;
    }
}

// ---------------- CSR aggregation (r13 version, fp16 gather) ----------------
__global__ void __launch_bounds__(ETPB) k_aggr(int layer) {
    __shared__ float sB;
    {
        float a = -3.4e38f, b = -3.4e38f;
        for (int i = threadIdx.x; i < NBG; i += ETPB) {
            a = fmaxf(a, g_pmax_s[i]);
            b = fmaxf(b, g_pmax_d[i]);
        }
#pragma unroll
        for (int o = 16; o; o >>= 1) {
            a = fmaxf(a, __shfl_xor_sync(0xffffffffu, a, o));
            b = fmaxf(b, __shfl_xor_sync(0xffffffffu, b, o));
        }
        __shared__ float ra[EWPB], rb[EWPB];
        if ((threadIdx.x & 31) == 0) { ra[threadIdx.x >> 5] = a; rb[threadIdx.x >> 5] = b; }
        __syncthreads();
        if (threadIdx.x == 0) {
            float ma = ra[0], mb = rb[0];
            for (int i = 1; i < EWPB; i++) { ma = fmaxf(ma, ra[i]); mb = fmaxf(mb, rb[i]); }
            sB = ma + mb;
        }
        __syncthreads();
    }
    const float B = sB;

    int lane = threadIdx.x & 31;
    int wid = threadIdx.x >> 5;

    float2* acc2 = reinterpret_cast<float2*>(layer ? g_hacc : g_h1);

    float psum = 0.0f;
    for (int d = blockIdx.x * EWPB + wid; d < NN; d += EWARPS) {
        int beg = g_rowptr[d];
        int end = g_rowptr[d + 1];
        float sdd = g_sdst[d];
        float2 A0 = make_float2(0.f, 0.f), A1 = A0;

        for (int c = beg; c < end; c += 32) {
            int e = c + lane;
            int s = 0; float p = 0.f;
            if (e < end) {
                s = g_csrc[e];
                float sc = g_ssrc[s] + sdd;
                if (sc > 0.f) p = expf(sc - B);
            }
            psum += p;

            unsigned act = __ballot_sync(0xffffffffu, p != 0.f);
            while (act) {
                int j0 = __ffs(act) - 1; act &= act - 1;
                int s0 = __shfl_sync(0xffffffffu, s, j0);
                float p0 = __shfl_sync(0xffffffffu, p, j0);
                if (act) {
                    int j1 = __ffs(act) - 1; act &= act - 1;
                    int s1 = __shfl_sync(0xffffffffu, s, j1);
                    float p1 = __shfl_sync(0xffffffffu, p, j1);
                    unsigned u0 = g_whh[(size_t)s0 * 32 + lane];
                    unsigned u1 = g_whh[(size_t)s1 * 32 + lane];
                    float2 x0 = __half22float2(*reinterpret_cast<__half2*>(&u0));
                    float2 x1 = __half22float2(*reinterpret_cast<__half2*>(&u1));
                    A0.x += p0 * x0.x; A0.y += p0 * x0.y;
                    A1.x += p1 * x1.x; A1.y += p1 * x1.y;
                } else {
                    unsigned u0 = g_whh[(size_t)s0 * 32 + lane];
                    float2 x0 = __half22float2(*reinterpret_cast<__half2*>(&u0));
                    A0.x += p0 * x0.x; A0.y += p0 * x0.y;
                }
            }
        }

        float2 R;
        R.x = A0.x + A1.x;
        R.y = A0.y + A1.y;
        acc2[(size_t)d * 32 + lane] = R;
    }

#pragma unroll
    for (int o = 16; o; o >>= 1) psum += __shfl_xor_sync(0xffffffffu, psum, o);
    __shared__ float sm2[EWPB];
    if (lane == 0) sm2[wid] = psum;
    __syncthreads();
    if (threadIdx.x == 0) {
        float t = 0.0f;
        for (int i = 0; i < EWPB; i++) t += sm2[i];
        g_psum[blockIdx.x] = t;
    }
}

// ---------------- output head (unchanged) ----------------
__global__ void __launch_bounds__(NTPB, 2) k_out(const float* __restrict__ W,
                                                 const float* __restrict__ b,
                                                 float* __restrict__ out) {
    __shared__ __align__(16) float sW[HIDD * NC];
    __shared__ float sb[NC];
    __shared__ float sInv;
    int tid = threadIdx.x;
    for (int i = tid; i < HIDD * NC; i += NTPB) sW[i] = W[i];
    if (tid < NC) sb[tid] = b[tid];
    {
        float t = 0.0f;
        for (int i = tid; i < EGRID; i += NTPB) t += g_psum[i];
#pragma unroll
        for (int o = 16; o; o >>= 1) t += __shfl_xor_sync(0xffffffffu, t, o);
        __shared__ float sm[8];
        if ((tid & 31) == 0) sm[tid >> 5] = t;
        __syncthreads();
        if (tid == 0) {
            float s = 0.0f;
            for (int i = 0; i < 8; i++) s += sm[i];
            sInv = (s > 0.0f) ? (1.0f / s) : 0.0f;
        }
    }
    __syncthreads();
    float inv = sInv;

    int jq = tid & 3;
    int n0 = blockIdx.x * 256 + (tid >> 2) * 4;
    bool av[4]; int nn[4];
#pragma unroll
    for (int i = 0; i < 4; i++) {
        int n = n0 + i;
        av[i] = (n < NN);
        nn[i] = av[i] ? n : 0;
    }

    ull acc[4][5];
#pragma unroll
    for (int i = 0; i < 4; i++)
#pragma unroll
        for (int j = 0; j < 5; j++)
            acc[i][j] = pk2(sb[jq * 10 + 2 * j], sb[jq * 10 + 2 * j + 1]);

    const char* wbase = reinterpret_cast<const char*>(sW) + jq * 40;

    for (int k4 = 0; k4 < HIDD / 4; k4++) {
        float4 f[4];
#pragma unroll
        for (int i = 0; i < 4; i++) {
            float4 t = g_hacc[(size_t)nn[i] * 16 + k4];
            t.x = eluf(t.x * inv); t.y = eluf(t.y * inv);
            t.z = eluf(t.z * inv); t.w = eluf(t.w * inv);
            f[i] = t;
        }
#pragma unroll
        for (int q = 0; q < 4; q++) {
            ull hp[4];
            hp[0] = dup2(q == 0 ? f[0].x : q == 1 ? f[0].y : q == 2 ? f[0].z : f[0].w);
            hp[1] = dup2(q == 0 ? f[1].x : q == 1 ? f[1].y : q == 2 ? f[1].z : f[1].w);
            hp[2] = dup2(q == 0 ? f[2].x : q == 1 ? f[2].y : q == 2 ? f[2].z : f[2].w);
            hp[3] = dup2(q == 0 ? f[3].x : q == 1 ? f[3].y : q == 2 ? f[3].z : f[3].w);
            const ull* wrow = reinterpret_cast<const ull*>(wbase + (k4 * 4 + q) * (NC * 4));
#pragma unroll
            for (int j = 0; j < 5; j++) {
                ull wv = wrow[j];
#pragma unroll
                for (int i = 0; i < 4; i++) ffma2(acc[i][j], hp[i], wv);
            }
        }
    }

#pragma unroll
    for (int i = 0; i < 4; i++) {
        float v[10];
#pragma unroll
        for (int j = 0; j < 5; j++) {
            float2 u = upk2(acc[i][j]);
            v[2 * j] = u.x;
            v[2 * j + 1] = u.y;
        }
        float m = -3.4e38f;
#pragma unroll
        for (int j = 0; j < 10; j++) {
            v[j] = (v[j] > 0.f) ? v[j] : (expf(v[j]) - 1.f);
            m = fmaxf(m, v[j]);
        }
        m = fmaxf(m, __shfl_xor_sync(0xffffffffu, m, 1));
        m = fmaxf(m, __shfl_xor_sync(0xffffffffu, m, 2));

        float se = 0.f;
#pragma unroll
        for (int j = 0; j < 10; j++) se += expf(v[j] - m);
        se += __shfl_xor_sync(0xffffffffu, se, 1);
        se += __shfl_xor_sync(0xffffffffu, se, 2);
        float lse = m + logf(se);

        if (av[i]) {
            float* o = out + (size_t)nn[i] * NC + jq * 10;
#pragma unroll
            for (int j = 0; j < 10; j++) o[j] = v[j] - lse;
        }
    }
}

// ---------------- launch ----------------
extern "C" void kernel_launch(void* const* d_in, const int* in_sizes, int n_in,
                              void* d_out, int out_size) {
    const float* x      = (const float*)d_in[0];
    const void*  ei     = (const void*)d_in[1];
    const float* emb_w  = (const float*)d_in[2];
    const float* emb_b  = (const float*)d_in[3];
    const float* Ws     = (const float*)d_in[4];
    const float* attn_a = (const float*)d_in[5];
    const float* out_w  = (const float*)d_in[6];
    const float* out_b  = (const float*)d_in[7];
    float* out          = (float*)d_out;

    (void)in_sizes; (void)n_in; (void)out_size;

    const int EB = (EE + 255) / 256;
    const int NB = (NN + 255) / 256;

    k_detect_zdeg<<<NB, 256>>>((const int*)ei);
    k_hist<<<EB, 256>>>(ei);
    k_scan1<<<SCAN_BLKS, 256>>>();
    k_scan2<<<1, 512>>>();
    k_scan3<<<NB, 256>>>();
    k_scat<<<EB, 256>>>();

    k_emb<<<NBG, NTPB>>>(x, emb_w, emb_b);

    for (int l = 0; l < 2; l++) {
        k_gemm_s<<<NBG, NTPB>>>(l, Ws + l * HIDD * HIDD, attn_a + l * 2 * HIDD);
        k_aggr<<<EGRID, ETPB>>>(l);
    }

    k_out<<<NBG, NTPB>>>(out_w, out_b, out);
}

// round 15
// speedup vs baseline: 1.3967x; 1.1540x over previous
#include <cuda_runtime.h>
#include <cuda_fp16.h>

#define NN 100000
#define EE 1600000
#define IND 128
#define HIDD 64
#define NC 40

#define NBG 391               // ceil(NN / 256)
#define NTPB 256
#define EGRID 1184
#define ETPB 256
#define EWPB (ETPB / 32)
#define EWARPS (EGRID * EWPB)
#define SCAN_BLKS 391

typedef unsigned long long ull;

// ---------------- device scratch ----------------
__device__ float4   g_h0[NN * 16];
__device__ float4   g_h1[NN * 16];
__device__ float4   g_hacc[NN * 16];
__device__ unsigned g_whh[NN * 32];   // wh rows, half2-packed
__device__ float    g_ssrc[NN];
__device__ float    g_sdst[NN];
__device__ float    g_pmax_s[NBG];
__device__ float    g_pmax_d[NBG];
__device__ float    g_psum[EGRID];
__device__ int      g_is64;
__device__ int2     g_epack[EE];
__device__ int      g_deg[NN];
__device__ int      g_rp[NN];
__device__ int      g_btot[SCAN_BLKS];
__device__ int      g_boff[SCAN_BLKS];
__device__ int      g_rowptr[NN + 1];
__device__ int      g_cursor[NN];
__device__ int      g_csrc[EE];

// ---------------- helpers ----------------
__device__ __forceinline__ ull pk2(float a, float b) {
    ull r;
    asm("mov.b64 %0, {%1, %2};" : "=l"(r) : "f"(a), "f"(b));
    return r;
}
__device__ __forceinline__ ull dup2(float a) { return pk2(a, a); }
__device__ __forceinline__ float2 upk2(ull v) {
    float2 r;
    asm("mov.b64 {%0, %1}, %2;" : "=f"(r.x), "=f"(r.y) : "l"(v));
    return r;
}
__device__ __forceinline__ void ffma2(ull& acc, ull a, ull b) {
    asm("fma.rn.f32x2 %0, %1, %2, %0;" : "+l"(acc) : "l"(a), "l"(b));
}
__device__ __forceinline__ float eluf(float x) { return x > 0.f ? x : (expf(x) - 1.f); }

__device__ __forceinline__ void mma16816(float* c, const unsigned* a, unsigned b0, unsigned b1) {
    asm volatile(
        "mma.sync.aligned.m16n8k16.row.col.f32.f16.f16.f32 "
        "{%0,%1,%2,%3}, {%4,%5,%6,%7}, {%8,%9}, {%0,%1,%2,%3};"
        : "+f"(c[0]), "+f"(c[1]), "+f"(c[2]), "+f"(c[3])
        : "r"(a[0]), "r"(a[1]), "r"(a[2]), "r"(a[3]), "r"(b0), "r"(b1));
}

// ---------------- dtype detect + zero degrees ----------------
__global__ void k_detect_zdeg(const int* __restrict__ ei32) {
    int i = blockIdx.x * blockDim.x + threadIdx.x;
    if (i < NN) g_deg[i] = 0;
    if (blockIdx.x == 0) {
        int nz = 0;
        for (int k = threadIdx.x; k < 1024; k += blockDim.x)
            if (ei32[2 * k + 1] != 0) nz = 1;
        int cnt = __syncthreads_count(nz);
        if (threadIdx.x == 0) g_is64 = (cnt == 0) ? 1 : 0;
    }
}

// ---------------- CSR build ----------------
__global__ void k_hist(const void* __restrict__ ei) {
    int is64 = g_is64;
    int e = blockIdx.x * blockDim.x + threadIdx.x;
    if (e >= EE) return;
    int s, d;
    if (is64) {
        s = (int)((const long long*)ei)[e];
        d = (int)((const long long*)ei)[EE + e];
    } else {
        s = ((const int*)ei)[e];
        d = ((const int*)ei)[EE + e];
    }
    s = min(max(s, 0), NN - 1);
    d = min(max(d, 0), NN - 1);
    g_epack[e] = make_int2(s, d);
    atomicAdd(&g_deg[d], 1);
}

__global__ void k_scan1() {
    __shared__ int sm[256];
    int i = blockIdx.x * 256 + threadIdx.x;
    int v = (i < NN) ? g_deg[i] : 0;
    sm[threadIdx.x] = v;
    __syncthreads();
    for (int off = 1; off < 256; off <<= 1) {
        int t = (threadIdx.x >= off) ? sm[threadIdx.x - off] : 0;
        __syncthreads();
        sm[threadIdx.x] += t;
        __syncthreads();
    }
    int incl = sm[threadIdx.x];
    if (i < NN) g_rp[i] = incl - v;
    if (threadIdx.x == 255) g_btot[blockIdx.x] = incl;
}

__global__ void k_scan2() {
    __shared__ int sm[512];
    int tid = threadIdx.x;
    int v = (tid < SCAN_BLKS) ? g_btot[tid] : 0;
    sm[tid] = v;
    __syncthreads();
    for (int off = 1; off < 512; off <<= 1) {
        int t = (tid >= off) ? sm[tid - off] : 0;
        __syncthreads();
        sm[tid] += t;
        __syncthreads();
    }
    if (tid < SCAN_BLKS) g_boff[tid] = sm[tid] - v;
}

__global__ void k_scan3() {
    int i = blockIdx.x * blockDim.x + threadIdx.x;
    if (i < NN) {
        int rp = g_rp[i] + g_boff[i >> 8];
        g_rowptr[i] = rp;
        g_cursor[i] = rp;
    }
    if (i == 0) g_rowptr[NN] = EE;
}

__global__ void k_scat() {
    int e = blockIdx.x * blockDim.x + threadIdx.x;
    if (e >= EE) return;
    int2 sd = g_epack[e];
    int pos = atomicAdd(&g_cursor[sd.y], 1);
    g_csrc[pos] = sd.x;
}

#define HSTRIDE 72

// ---------------- embedding via tensor cores: h0 = x @ emb_w + emb_b ----------------
// 256 threads = 8 warps, 256 nodes/block; K=128 processed as two staged halves of 64.
__global__ void __launch_bounds__(NTPB, 2) k_emb(const float* __restrict__ x,
                                                 const float* __restrict__ w,
                                                 const float* __restrict__ b) {
    __shared__ __half sH[256 * HSTRIDE];   // 36864 B
    __shared__ __half sWt[64 * HSTRIDE];   // 9216 B, n-major
    __shared__ float sb[HIDD];
    int tid = threadIdx.x;
    if (tid < HIDD) sb[tid] = b[tid];

    int node = blockIdx.x * 256 + tid;
    int nc = (node < NN) ? node : 0;

    int wp = tid >> 5;
    int lane = tid & 31;
    int grp = lane >> 2;
    int qid = lane & 3;

    float c[2][8][4];
#pragma unroll
    for (int mt = 0; mt < 2; mt++)
#pragma unroll
        for (int nt = 0; nt < 8; nt++)
#pragma unroll
            for (int q = 0; q < 4; q++) c[mt][nt][q] = 0.f;

    for (int half = 0; half < 2; half++) {
        __syncthreads();   // previous iteration's MMA reads done before restage
        // stage W^T for this K-half: w is [128,64] row-major
        for (int i = tid; i < 64 * 64; i += NTPB) {
            int k = i >> 6, n = i & 63;
            sWt[n * HSTRIDE + k] = __float2half(w[(half * 64 + k) * HIDD + n]);
        }
        // stage x half for row tid
        {
            const float4* xr = reinterpret_cast<const float4*>(x + (size_t)nc * IND + half * 64);
            __half2* dst = reinterpret_cast<__half2*>(sH + tid * HSTRIDE);
#pragma unroll
            for (int k4 = 0; k4 < 16; k4++) {
                float4 v = xr[k4];
                dst[2 * k4]     = __floats2half2_rn(v.x, v.y);
                dst[2 * k4 + 1] = __floats2half2_rn(v.z, v.w);
            }
        }
        __syncthreads();

#pragma unroll
        for (int kc = 0; kc < 4; kc++) {
            int k0 = kc * 16 + 2 * qid;
            unsigned a[2][4];
#pragma unroll
            for (int mt = 0; mt < 2; mt++) {
                const __half* base = sH + (wp * 32 + mt * 16 + grp) * HSTRIDE;
                a[mt][0] = *reinterpret_cast<const unsigned*>(base + k0);
                a[mt][1] = *reinterpret_cast<const unsigned*>(base + 8 * HSTRIDE + k0);
                a[mt][2] = *reinterpret_cast<const unsigned*>(base + k0 + 8);
                a[mt][3] = *reinterpret_cast<const unsigned*>(base + 8 * HSTRIDE + k0 + 8);
            }
#pragma unroll
            for (int nt = 0; nt < 8; nt++) {
                const __half* bb = sWt + (nt * 8 + grp) * HSTRIDE + k0;
                unsigned b0 = *reinterpret_cast<const unsigned*>(bb);
                unsigned b1 = *reinterpret_cast<const unsigned*>(bb + 8);
                mma16816(c[0][nt], a[0], b0, b1);
                mma16816(c[1][nt], a[1], b0, b1);
            }
        }
    }

    // epilogue: add bias, store fp32 h0 as float2 fragments
    float2* h0f2 = reinterpret_cast<float2*>(g_h0);
#pragma unroll
    for (int mt = 0; mt < 2; mt++) {
        int row0 = wp * 32 + mt * 16 + grp;
        int row1 = row0 + 8;
        int node0 = blockIdx.x * 256 + row0;
        int node1 = blockIdx.x * 256 + row1;
#pragma unroll
        for (int nt = 0; nt < 8; nt++) {
            int col = nt * 8 + 2 * qid;
            float b0v = sb[col], b1v = sb[col + 1];
            int pidx = nt * 4 + qid;
            if (node0 < NN)
                h0f2[(size_t)node0 * 32 + pidx] = make_float2(c[mt][nt][0] + b0v, c[mt][nt][1] + b1v);
            if (node1 < NN)
                h0f2[(size_t)node1 * 32 + pidx] = make_float2(c[mt][nt][2] + b0v, c[mt][nt][3] + b1v);
        }
    }
}

// ---------------- per-layer GEMM via tensor cores (r14, unchanged) ----------------
__global__ void __launch_bounds__(NTPB, 2) k_gemm_s(int layer,
                                                    const float* __restrict__ W,
                                                    const float* __restrict__ avec) {
    __shared__ __half sH[256 * HSTRIDE];
    __shared__ __half sWt[64 * HSTRIDE];
    __shared__ float sa[2 * HIDD];
    __shared__ float sInv;
    int tid = threadIdx.x;

    if (tid < 2 * HIDD) sa[tid] = avec[tid];

    if (layer) {
        float t = 0.0f;
        for (int i = tid; i < EGRID; i += NTPB) t += g_psum[i];
#pragma unroll
        for (int o = 16; o; o >>= 1) t += __shfl_xor_sync(0xffffffffu, t, o);
        __shared__ float smr[8];
        if ((tid & 31) == 0) smr[tid >> 5] = t;
        __syncthreads();
        if (tid == 0) {
            float s = 0.0f;
            for (int i = 0; i < 8; i++) s += smr[i];
            sInv = (s > 0.0f) ? (1.0f / s) : 0.0f;
        }
        __syncthreads();
    }
    float inv = layer ? sInv : 1.0f;

    for (int i = tid; i < HIDD * HIDD; i += NTPB) {
        int k = i >> 6, n = i & 63;
        sWt[n * HSTRIDE + k] = __float2half(W[i]);
    }

    {
        int node = blockIdx.x * 256 + tid;
        int nc = (node < NN) ? node : 0;
        const float4* hr = (layer ? g_h1 : g_h0) + (size_t)nc * 16;
        __half2* dst = reinterpret_cast<__half2*>(sH + tid * HSTRIDE);
#pragma unroll
        for (int k4 = 0; k4 < 16; k4++) {
            float4 v = hr[k4];
            if (layer) {
                v.x = eluf(v.x * inv); v.y = eluf(v.y * inv);
                v.z = eluf(v.z * inv); v.w = eluf(v.w * inv);
            }
            dst[2 * k4]     = __floats2half2_rn(v.x, v.y);
            dst[2 * k4 + 1] = __floats2half2_rn(v.z, v.w);
        }
    }
    __syncthreads();

    int w = tid >> 5;
    int lane = tid & 31;
    int grp = lane >> 2;
    int qid = lane & 3;

    float c[2][8][4];
#pragma unroll
    for (int mt = 0; mt < 2; mt++)
#pragma unroll
        for (int nt = 0; nt < 8; nt++)
#pragma unroll
            for (int q = 0; q < 4; q++) c[mt][nt][q] = 0.f;

#pragma unroll
    for (int kc = 0; kc < 4; kc++) {
        int k0 = kc * 16 + 2 * qid;
        unsigned a[2][4];
#pragma unroll
        for (int mt = 0; mt < 2; mt++) {
            const __half* base = sH + (w * 32 + mt * 16 + grp) * HSTRIDE;
            a[mt][0] = *reinterpret_cast<const unsigned*>(base + k0);
            a[mt][1] = *reinterpret_cast<const unsigned*>(base + 8 * HSTRIDE + k0);
            a[mt][2] = *reinterpret_cast<const unsigned*>(base + k0 + 8);
            a[mt][3] = *reinterpret_cast<const unsigned*>(base + 8 * HSTRIDE + k0 + 8);
        }
#pragma unroll
        for (int nt = 0; nt < 8; nt++) {
            const __half* bb = sWt + (nt * 8 + grp) * HSTRIDE + k0;
            unsigned b0 = *reinterpret_cast<const unsigned*>(bb);
            unsigned b1 = *reinterpret_cast<const unsigned*>(bb + 8);
            mma16816(c[0][nt], a[0], b0, b1);
            mma16816(c[1][nt], a[1], b0, b1);
        }
    }

    float rmax_s = -3.4e38f, rmax_d = -3.4e38f;
#pragma unroll
    for (int mt = 0; mt < 2; mt++) {
        float ss0 = 0.f, ss1 = 0.f, sd0 = 0.f, sd1 = 0.f;
#pragma unroll
        for (int nt = 0; nt < 8; nt++) {
            int col = nt * 8 + 2 * qid;
            float as0 = sa[col], as1 = sa[col + 1];
            float ad0 = sa[HIDD + col], ad1 = sa[HIDD + col + 1];
            ss0 += c[mt][nt][0] * as0 + c[mt][nt][1] * as1;
            sd0 += c[mt][nt][0] * ad0 + c[mt][nt][1] * ad1;
            ss1 += c[mt][nt][2] * as0 + c[mt][nt][3] * as1;
            sd1 += c[mt][nt][2] * ad0 + c[mt][nt][3] * ad1;
        }
        ss0 += __shfl_xor_sync(0xffffffffu, ss0, 1);
        ss0 += __shfl_xor_sync(0xffffffffu, ss0, 2);
        sd0 += __shfl_xor_sync(0xffffffffu, sd0, 1);
        sd0 += __shfl_xor_sync(0xffffffffu, sd0, 2);
        ss1 += __shfl_xor_sync(0xffffffffu, ss1, 1);
        ss1 += __shfl_xor_sync(0xffffffffu, ss1, 2);
        sd1 += __shfl_xor_sync(0xffffffffu, sd1, 1);
        sd1 += __shfl_xor_sync(0xffffffffu, sd1, 2);

        int row0 = w * 32 + mt * 16 + grp;
        int row1 = row0 + 8;
        int node0 = blockIdx.x * 256 + row0;
        int node1 = blockIdx.x * 256 + row1;

        if (qid == 0) {
            if (node0 < NN) { g_ssrc[node0] = ss0; g_sdst[node0] = sd0; }
            if (node1 < NN) { g_ssrc[node1] = ss1; g_sdst[node1] = sd1; }
        }
        if (node0 < NN) { rmax_s = fmaxf(rmax_s, ss0); rmax_d = fmaxf(rmax_d, sd0); }
        if (node1 < NN) { rmax_s = fmaxf(rmax_s, ss1); rmax_d = fmaxf(rmax_d, sd1); }

#pragma unroll
        for (int nt = 0; nt < 8; nt++) {
            int pidx = qid + nt * 4;
            if (node0 < NN) {
                __half2 h0 = __floats2half2_rn(c[mt][nt][0], c[mt][nt][1]);
                g_whh[(size_t)node0 * 32 + pidx] = *reinterpret_cast<unsigned*>(&h0);
            }
            if (node1 < NN) {
                __half2 h1 = __floats2half2_rn(c[mt][nt][2], c[mt][nt][3]);
                g_whh[(size_t)node1 * 32 + pidx] = *reinterpret_cast<unsigned*>(&h1);
            }
        }
    }

#pragma unroll
    for (int o = 16; o; o >>= 1) {
        rmax_s = fmaxf(rmax_s, __shfl_xor_sync(0xffffffffu, rmax_s, o));
        rmax_d = fmaxf(rmax_d, __shfl_xor_sync(0xffffffffu, rmax_d, o));
    }
    __shared__ float sms[8], smd[8];
    if (lane == 0) { sms[w] = rmax_s; smd[w] = rmax_d; }
    __syncthreads();
    if (tid == 0) {
        float a = sms[0], b = smd[0];
        for (int i = 1; i < 8; i++) { a = fmaxf(a, sms[i]); b = fmaxf(b, smd[i]); }
        g_pmax_s[blockIdx.x] = a;
        g_pmax_d[blockIdx.x] = b;
    }
}

// ---------------- CSR aggregation (fp16 gather, unchanged) ----------------
__global__ void __launch_bounds__(ETPB) k_aggr(int layer) {
    __shared__ float sB;
    {
        float a = -3.4e38f, b = -3.4e38f;
        for (int i = threadIdx.x; i < NBG; i += ETPB) {
            a = fmaxf(a, g_pmax_s[i]);
            b = fmaxf(b, g_pmax_d[i]);
        }
#pragma unroll
        for (int o = 16; o; o >>= 1) {
            a = fmaxf(a, __shfl_xor_sync(0xffffffffu, a, o));
            b = fmaxf(b, __shfl_xor_sync(0xffffffffu, b, o));
        }
        __shared__ float ra[EWPB], rb[EWPB];
        if ((threadIdx.x & 31) == 0) { ra[threadIdx.x >> 5] = a; rb[threadIdx.x >> 5] = b; }
        __syncthreads();
        if (threadIdx.x == 0) {
            float ma = ra[0], mb = rb[0];
            for (int i = 1; i < EWPB; i++) { ma = fmaxf(ma, ra[i]); mb = fmaxf(mb, rb[i]); }
            sB = ma + mb;
        }
        __syncthreads();
    }
    const float B = sB;

    int lane = threadIdx.x & 31;
    int wid = threadIdx.x >> 5;

    float2* acc2 = reinterpret_cast<float2*>(layer ? g_hacc : g_h1);

    float psum = 0.0f;
    for (int d = blockIdx.x * EWPB + wid; d < NN; d += EWARPS) {
        int beg = g_rowptr[d];
        int end = g_rowptr[d + 1];
        float sdd = g_sdst[d];
        float2 A0 = make_float2(0.f, 0.f), A1 = A0;

        for (int c = beg; c < end; c += 32) {
            int e = c + lane;
            int s = 0; float p = 0.f;
            if (e < end) {
                s = g_csrc[e];
                float sc = g_ssrc[s] + sdd;
                if (sc > 0.f) p = expf(sc - B);
            }
            psum += p;

            unsigned act = __ballot_sync(0xffffffffu, p != 0.f);
            while (act) {
                int j0 = __ffs(act) - 1; act &= act - 1;
                int s0 = __shfl_sync(0xffffffffu, s, j0);
                float p0 = __shfl_sync(0xffffffffu, p, j0);
                if (act) {
                    int j1 = __ffs(act) - 1; act &= act - 1;
                    int s1 = __shfl_sync(0xffffffffu, s, j1);
                    float p1 = __shfl_sync(0xffffffffu, p, j1);
                    unsigned u0 = g_whh[(size_t)s0 * 32 + lane];
                    unsigned u1 = g_whh[(size_t)s1 * 32 + lane];
                    float2 x0 = __half22float2(*reinterpret_cast<__half2*>(&u0));
                    float2 x1 = __half22float2(*reinterpret_cast<__half2*>(&u1));
                    A0.x += p0 * x0.x; A0.y += p0 * x0.y;
                    A1.x += p1 * x1.x; A1.y += p1 * x1.y;
                } else {
                    unsigned u0 = g_whh[(size_t)s0 * 32 + lane];
                    float2 x0 = __half22float2(*reinterpret_cast<__half2*>(&u0));
                    A0.x += p0 * x0.x; A0.y += p0 * x0.y;
                }
            }
        }

        float2 R;
        R.x = A0.x + A1.x;
        R.y = A0.y + A1.y;
        acc2[(size_t)d * 32 + lane] = R;
    }

#pragma unroll
    for (int o = 16; o; o >>= 1) psum += __shfl_xor_sync(0xffffffffu, psum, o);
    __shared__ float sm2[EWPB];
    if (lane == 0) sm2[wid] = psum;
    __syncthreads();
    if (threadIdx.x == 0) {
        float t = 0.0f;
        for (int i = 0; i < EWPB; i++) t += sm2[i];
        g_psum[blockIdx.x] = t;
    }
}

// ---------------- output head (unchanged) ----------------
__global__ void __launch_bounds__(NTPB, 2) k_out(const float* __restrict__ W,
                                                 const float* __restrict__ b,
                                                 float* __restrict__ out) {
    __shared__ __align__(16) float sW[HIDD * NC];
    __shared__ float sb[NC];
    __shared__ float sInv;
    int tid = threadIdx.x;
    for (int i = tid; i < HIDD * NC; i += NTPB) sW[i] = W[i];
    if (tid < NC) sb[tid] = b[tid];
    {
        float t = 0.0f;
        for (int i = tid; i < EGRID; i += NTPB) t += g_psum[i];
#pragma unroll
        for (int o = 16; o; o >>= 1) t += __shfl_xor_sync(0xffffffffu, t, o);
        __shared__ float sm[8];
        if ((tid & 31) == 0) sm[tid >> 5] = t;
        __syncthreads();
        if (tid == 0) {
            float s = 0.0f;
            for (int i = 0; i < 8; i++) s += sm[i];
            sInv = (s > 0.0f) ? (1.0f / s) : 0.0f;
        }
    }
    __syncthreads();
    float inv = sInv;

    int jq = tid & 3;
    int n0 = blockIdx.x * 256 + (tid >> 2) * 4;
    bool av[4]; int nn[4];
#pragma unroll
    for (int i = 0; i < 4; i++) {
        int n = n0 + i;
        av[i] = (n < NN);
        nn[i] = av[i] ? n : 0;
    }

    ull acc[4][5];
#pragma unroll
    for (int i = 0; i < 4; i++)
#pragma unroll
        for (int j = 0; j < 5; j++)
            acc[i][j] = pk2(sb[jq * 10 + 2 * j], sb[jq * 10 + 2 * j + 1]);

    const char* wbase = reinterpret_cast<const char*>(sW) + jq * 40;

    for (int k4 = 0; k4 < HIDD / 4; k4++) {
        float4 f[4];
#pragma unroll
        for (int i = 0; i < 4; i++) {
            float4 t = g_hacc[(size_t)nn[i] * 16 + k4];
            t.x = eluf(t.x * inv); t.y = eluf(t.y * inv);
            t.z = eluf(t.z * inv); t.w = eluf(t.w * inv);
            f[i] = t;
        }
#pragma unroll
        for (int q = 0; q < 4; q++) {
            ull hp[4];
            hp[0] = dup2(q == 0 ? f[0].x : q == 1 ? f[0].y : q == 2 ? f[0].z : f[0].w);
            hp[1] = dup2(q == 0 ? f[1].x : q == 1 ? f[1].y : q == 2 ? f[1].z : f[1].w);
            hp[2] = dup2(q == 0 ? f[2].x : q == 1 ? f[2].y : q == 2 ? f[2].z : f[2].w);
            hp[3] = dup2(q == 0 ? f[3].x : q == 1 ? f[3].y : q == 2 ? f[3].z : f[3].w);
            const ull* wrow = reinterpret_cast<const ull*>(wbase + (k4 * 4 + q) * (NC * 4));
#pragma unroll
            for (int j = 0; j < 5; j++) {
                ull wv = wrow[j];
#pragma unroll
                for (int i = 0; i < 4; i++) ffma2(acc[i][j], hp[i], wv);
            }
        }
    }

#pragma unroll
    for (int i = 0; i < 4; i++) {
        float v[10];
#pragma unroll
        for (int j = 0; j < 5; j++) {
            float2 u = upk2(acc[i][j]);
            v[2 * j] = u.x;
            v[2 * j + 1] = u.y;
        }
        float m = -3.4e38f;
#pragma unroll
        for (int j = 0; j < 10; j++) {
            v[j] = (v[j] > 0.f) ? v[j] : (expf(v[j]) - 1.f);
            m = fmaxf(m, v[j]);
        }
        m = fmaxf(m, __shfl_xor_sync(0xffffffffu, m, 1));
        m = fmaxf(m, __shfl_xor_sync(0xffffffffu, m, 2));

        float se = 0.f;
#pragma unroll
        for (int j = 0; j < 10; j++) se += expf(v[j] - m);
        se += __shfl_xor_sync(0xffffffffu, se, 1);
        se += __shfl_xor_sync(0xffffffffu, se, 2);
        float lse = m + logf(se);

        if (av[i]) {
            float* o = out + (size_t)nn[i] * NC + jq * 10;
#pragma unroll
            for (int j = 0; j < 10; j++) o[j] = v[j] - lse;
        }
    }
}

// ---------------- launch ----------------
extern "C" void kernel_launch(void* const* d_in, const int* in_sizes, int n_in,
                              void* d_out, int out_size) {
    const float* x      = (const float*)d_in[0];
    const void*  ei     = (const void*)d_in[1];
    const float* emb_w  = (const float*)d_in[2];
    const float* emb_b  = (const float*)d_in[3];
    const float* Ws     = (const float*)d_in[4];
    const float* attn_a = (const float*)d_in[5];
    const float* out_w  = (const float*)d_in[6];
    const float* out_b  = (const float*)d_in[7];
    float* out          = (float*)d_out;

    (void)in_sizes; (void)n_in; (void)out_size;

    const int EB = (EE + 255) / 256;
    const int NB = (NN + 255) / 256;

    k_detect_zdeg<<<NB, 256>>>((const int*)ei);
    k_hist<<<EB, 256>>>(ei);
    k_scan1<<<SCAN_BLKS, 256>>>();
    k_scan2<<<1, 512>>>();
    k_scan3<<<NB, 256>>>();
    k_scat<<<EB, 256>>>();

    k_emb<<<NBG, NTPB>>>(x, emb_w, emb_b);

    for (int l = 0; l < 2; l++) {
        k_gemm_s<<<NBG, NTPB>>>(l, Ws + l * HIDD * HIDD, attn_a + l * 2 * HIDD);
        k_aggr<<<EGRID, ETPB>>>(l);
    }

    k_out<<<NBG, NTPB>>>(out_w, out_b, out);
}

// round 16
// speedup vs baseline: 1.5824x; 1.1330x over previous
#include <cuda_runtime.h>
#include <cuda_fp16.h>

#define NN 100000
#define EE 1600000
#define IND 128
#define HIDD 64
#define NC 40

#define NBG 391               // ceil(NN / 256)
#define NTPB 256
#define EGRID 1184
#define ETPB 256
#define EWPB (ETPB / 32)
#define EWARPS (EGRID * EWPB)
#define SCAN_BLKS 391

typedef unsigned long long ull;

// ---------------- device scratch ----------------
__device__ float4   g_h0[NN * 16];
__device__ float4   g_h1[NN * 16];
__device__ float4   g_hacc[NN * 16];
__device__ unsigned g_whh[NN * 32];   // wh rows, half2-packed
__device__ float    g_ssrc[NN];
__device__ float    g_sdst[NN];
__device__ float    g_pmax_s[NBG];
__device__ float    g_pmax_d[NBG];
__device__ float    g_psum[EGRID];
__device__ int      g_is64;
__device__ int2     g_epack[EE];
__device__ int      g_deg[NN];
__device__ int      g_rp[NN];
__device__ int      g_btot[SCAN_BLKS];
__device__ int      g_boff[SCAN_BLKS];
__device__ int      g_rowptr[NN + 1];
__device__ int      g_cursor[NN];
__device__ int      g_csrc[EE];

// ---------------- helpers ----------------
__device__ __forceinline__ float eluf(float x) { return x > 0.f ? x : (expf(x) - 1.f); }

__device__ __forceinline__ void mma16816(float* c, const unsigned* a, unsigned b0, unsigned b1) {
    asm volatile(
        "mma.sync.aligned.m16n8k16.row.col.f32.f16.f16.f32 "
        "{%0,%1,%2,%3}, {%4,%5,%6,%7}, {%8,%9}, {%0,%1,%2,%3};"
        : "+f"(c[0]), "+f"(c[1]), "+f"(c[2]), "+f"(c[3])
        : "r"(a[0]), "r"(a[1]), "r"(a[2]), "r"(a[3]), "r"(b0), "r"(b1));
}

// ---------------- dtype detect + zero degrees ----------------
__global__ void k_detect_zdeg(const int* __restrict__ ei32) {
    int i = blockIdx.x * blockDim.x + threadIdx.x;
    if (i < NN) g_deg[i] = 0;
    if (blockIdx.x == 0) {
        int nz = 0;
        for (int k = threadIdx.x; k < 1024; k += blockDim.x)
            if (ei32[2 * k + 1] != 0) nz = 1;
        int cnt = __syncthreads_count(nz);
        if (threadIdx.x == 0) g_is64 = (cnt == 0) ? 1 : 0;
    }
}

// ---------------- CSR build ----------------
__global__ void k_hist(const void* __restrict__ ei) {
    int is64 = g_is64;
    int e = blockIdx.x * blockDim.x + threadIdx.x;
    if (e >= EE) return;
    int s, d;
    if (is64) {
        s = (int)((const long long*)ei)[e];
        d = (int)((const long long*)ei)[EE + e];
    } else {
        s = ((const int*)ei)[e];
        d = ((const int*)ei)[EE + e];
    }
    s = min(max(s, 0), NN - 1);
    d = min(max(d, 0), NN - 1);
    g_epack[e] = make_int2(s, d);
    atomicAdd(&g_deg[d], 1);
}

__global__ void k_scan1() {
    __shared__ int sm[256];
    int i = blockIdx.x * 256 + threadIdx.x;
    int v = (i < NN) ? g_deg[i] : 0;
    sm[threadIdx.x] = v;
    __syncthreads();
    for (int off = 1; off < 256; off <<= 1) {
        int t = (threadIdx.x >= off) ? sm[threadIdx.x - off] : 0;
        __syncthreads();
        sm[threadIdx.x] += t;
        __syncthreads();
    }
    int incl = sm[threadIdx.x];
    if (i < NN) g_rp[i] = incl - v;
    if (threadIdx.x == 255) g_btot[blockIdx.x] = incl;
}

__global__ void k_scan2() {
    __shared__ int sm[512];
    int tid = threadIdx.x;
    int v = (tid < SCAN_BLKS) ? g_btot[tid] : 0;
    sm[tid] = v;
    __syncthreads();
    for (int off = 1; off < 512; off <<= 1) {
        int t = (tid >= off) ? sm[tid - off] : 0;
        __syncthreads();
        sm[tid] += t;
        __syncthreads();
    }
    if (tid < SCAN_BLKS) g_boff[tid] = sm[tid] - v;
}

__global__ void k_scan3() {
    int i = blockIdx.x * blockDim.x + threadIdx.x;
    if (i < NN) {
        int rp = g_rp[i] + g_boff[i >> 8];
        g_rowptr[i] = rp;
        g_cursor[i] = rp;
    }
    if (i == 0) g_rowptr[NN] = EE;
}

__global__ void k_scat() {
    int e = blockIdx.x * blockDim.x + threadIdx.x;
    if (e >= EE) return;
    int2 sd = g_epack[e];
    int pos = atomicAdd(&g_cursor[sd.y], 1);
    g_csrc[pos] = sd.x;
}

#define HSTRIDE 72

// ---------------- embedding via tensor cores ----------------
__global__ void __launch_bounds__(NTPB, 2) k_emb(const float* __restrict__ x,
                                                 const float* __restrict__ w,
                                                 const float* __restrict__ b) {
    __shared__ __half sH[256 * HSTRIDE];
    __shared__ __half sWt[64 * HSTRIDE];
    __shared__ float sb[HIDD];
    int tid = threadIdx.x;
    if (tid < HIDD) sb[tid] = b[tid];

    int node = blockIdx.x * 256 + tid;
    int nc = (node < NN) ? node : 0;

    int wp = tid >> 5;
    int lane = tid & 31;
    int grp = lane >> 2;
    int qid = lane & 3;

    float c[2][8][4];
#pragma unroll
    for (int mt = 0; mt < 2; mt++)
#pragma unroll
        for (int nt = 0; nt < 8; nt++)
#pragma unroll
            for (int q = 0; q < 4; q++) c[mt][nt][q] = 0.f;

    for (int half = 0; half < 2; half++) {
        __syncthreads();
        for (int i = tid; i < 64 * 64; i += NTPB) {
            int k = i >> 6, n = i & 63;
            sWt[n * HSTRIDE + k] = __float2half(w[(half * 64 + k) * HIDD + n]);
        }
        {
            const float4* xr = reinterpret_cast<const float4*>(x + (size_t)nc * IND + half * 64);
            __half2* dst = reinterpret_cast<__half2*>(sH + tid * HSTRIDE);
#pragma unroll
            for (int k4 = 0; k4 < 16; k4++) {
                float4 v = xr[k4];
                dst[2 * k4]     = __floats2half2_rn(v.x, v.y);
                dst[2 * k4 + 1] = __floats2half2_rn(v.z, v.w);
            }
        }
        __syncthreads();

#pragma unroll
        for (int kc = 0; kc < 4; kc++) {
            int k0 = kc * 16 + 2 * qid;
            unsigned a[2][4];
#pragma unroll
            for (int mt = 0; mt < 2; mt++) {
                const __half* base = sH + (wp * 32 + mt * 16 + grp) * HSTRIDE;
                a[mt][0] = *reinterpret_cast<const unsigned*>(base + k0);
                a[mt][1] = *reinterpret_cast<const unsigned*>(base + 8 * HSTRIDE + k0);
                a[mt][2] = *reinterpret_cast<const unsigned*>(base + k0 + 8);
                a[mt][3] = *reinterpret_cast<const unsigned*>(base + 8 * HSTRIDE + k0 + 8);
            }
#pragma unroll
            for (int nt = 0; nt < 8; nt++) {
                const __half* bb = sWt + (nt * 8 + grp) * HSTRIDE + k0;
                unsigned b0 = *reinterpret_cast<const unsigned*>(bb);
                unsigned b1 = *reinterpret_cast<const unsigned*>(bb + 8);
                mma16816(c[0][nt], a[0], b0, b1);
                mma16816(c[1][nt], a[1], b0, b1);
            }
        }
    }

    float2* h0f2 = reinterpret_cast<float2*>(g_h0);
#pragma unroll
    for (int mt = 0; mt < 2; mt++) {
        int row0 = wp * 32 + mt * 16 + grp;
        int row1 = row0 + 8;
        int node0 = blockIdx.x * 256 + row0;
        int node1 = blockIdx.x * 256 + row1;
#pragma unroll
        for (int nt = 0; nt < 8; nt++) {
            int col = nt * 8 + 2 * qid;
            float b0v = sb[col], b1v = sb[col + 1];
            int pidx = nt * 4 + qid;
            if (node0 < NN)
                h0f2[(size_t)node0 * 32 + pidx] = make_float2(c[mt][nt][0] + b0v, c[mt][nt][1] + b1v);
            if (node1 < NN)
                h0f2[(size_t)node1 * 32 + pidx] = make_float2(c[mt][nt][2] + b0v, c[mt][nt][3] + b1v);
        }
    }
}

// ---------------- per-layer GEMM via tensor cores ----------------
__global__ void __launch_bounds__(NTPB, 2) k_gemm_s(int layer,
                                                    const float* __restrict__ W,
                                                    const float* __restrict__ avec) {
    __shared__ __half sH[256 * HSTRIDE];
    __shared__ __half sWt[64 * HSTRIDE];
    __shared__ float sa[2 * HIDD];
    __shared__ float sInv;
    int tid = threadIdx.x;

    if (tid < 2 * HIDD) sa[tid] = avec[tid];

    if (layer) {
        float t = 0.0f;
        for (int i = tid; i < EGRID; i += NTPB) t += g_psum[i];
#pragma unroll
        for (int o = 16; o; o >>= 1) t += __shfl_xor_sync(0xffffffffu, t, o);
        __shared__ float smr[8];
        if ((tid & 31) == 0) smr[tid >> 5] = t;
        __syncthreads();
        if (tid == 0) {
            float s = 0.0f;
            for (int i = 0; i < 8; i++) s += smr[i];
            sInv = (s > 0.0f) ? (1.0f / s) : 0.0f;
        }
        __syncthreads();
    }
    float inv = layer ? sInv : 1.0f;

    for (int i = tid; i < HIDD * HIDD; i += NTPB) {
        int k = i >> 6, n = i & 63;
        sWt[n * HSTRIDE + k] = __float2half(W[i]);
    }

    {
        int node = blockIdx.x * 256 + tid;
        int nc = (node < NN) ? node : 0;
        const float4* hr = (layer ? g_h1 : g_h0) + (size_t)nc * 16;
        __half2* dst = reinterpret_cast<__half2*>(sH + tid * HSTRIDE);
#pragma unroll
        for (int k4 = 0; k4 < 16; k4++) {
            float4 v = hr[k4];
            if (layer) {
                v.x = eluf(v.x * inv); v.y = eluf(v.y * inv);
                v.z = eluf(v.z * inv); v.w = eluf(v.w * inv);
            }
            dst[2 * k4]     = __floats2half2_rn(v.x, v.y);
            dst[2 * k4 + 1] = __floats2half2_rn(v.z, v.w);
        }
    }
    __syncthreads();

    int w = tid >> 5;
    int lane = tid & 31;
    int grp = lane >> 2;
    int qid = lane & 3;

    float c[2][8][4];
#pragma unroll
    for (int mt = 0; mt < 2; mt++)
#pragma unroll
        for (int nt = 0; nt < 8; nt++)
#pragma unroll
            for (int q = 0; q < 4; q++) c[mt][nt][q] = 0.f;

#pragma unroll
    for (int kc = 0; kc < 4; kc++) {
        int k0 = kc * 16 + 2 * qid;
        unsigned a[2][4];
#pragma unroll
        for (int mt = 0; mt < 2; mt++) {
            const __half* base = sH + (w * 32 + mt * 16 + grp) * HSTRIDE;
            a[mt][0] = *reinterpret_cast<const unsigned*>(base + k0);
            a[mt][1] = *reinterpret_cast<const unsigned*>(base + 8 * HSTRIDE + k0);
            a[mt][2] = *reinterpret_cast<const unsigned*>(base + k0 + 8);
            a[mt][3] = *reinterpret_cast<const unsigned*>(base + 8 * HSTRIDE + k0 + 8);
        }
#pragma unroll
        for (int nt = 0; nt < 8; nt++) {
            const __half* bb = sWt + (nt * 8 + grp) * HSTRIDE + k0;
            unsigned b0 = *reinterpret_cast<const unsigned*>(bb);
            unsigned b1 = *reinterpret_cast<const unsigned*>(bb + 8);
            mma16816(c[0][nt], a[0], b0, b1);
            mma16816(c[1][nt], a[1], b0, b1);
        }
    }

    float rmax_s = -3.4e38f, rmax_d = -3.4e38f;
#pragma unroll
    for (int mt = 0; mt < 2; mt++) {
        float ss0 = 0.f, ss1 = 0.f, sd0 = 0.f, sd1 = 0.f;
#pragma unroll
        for (int nt = 0; nt < 8; nt++) {
            int col = nt * 8 + 2 * qid;
            float as0 = sa[col], as1 = sa[col + 1];
            float ad0 = sa[HIDD + col], ad1 = sa[HIDD + col + 1];
            ss0 += c[mt][nt][0] * as0 + c[mt][nt][1] * as1;
            sd0 += c[mt][nt][0] * ad0 + c[mt][nt][1] * ad1;
            ss1 += c[mt][nt][2] * as0 + c[mt][nt][3] * as1;
            sd1 += c[mt][nt][2] * ad0 + c[mt][nt][3] * ad1;
        }
        ss0 += __shfl_xor_sync(0xffffffffu, ss0, 1);
        ss0 += __shfl_xor_sync(0xffffffffu, ss0, 2);
        sd0 += __shfl_xor_sync(0xffffffffu, sd0, 1);
        sd0 += __shfl_xor_sync(0xffffffffu, sd0, 2);
        ss1 += __shfl_xor_sync(0xffffffffu, ss1, 1);
        ss1 += __shfl_xor_sync(0xffffffffu, ss1, 2);
        sd1 += __shfl_xor_sync(0xffffffffu, sd1, 1);
        sd1 += __shfl_xor_sync(0xffffffffu, sd1, 2);

        int row0 = w * 32 + mt * 16 + grp;
        int row1 = row0 + 8;
        int node0 = blockIdx.x * 256 + row0;
        int node1 = blockIdx.x * 256 + row1;

        if (qid == 0) {
            if (node0 < NN) { g_ssrc[node0] = ss0; g_sdst[node0] = sd0; }
            if (node1 < NN) { g_ssrc[node1] = ss1; g_sdst[node1] = sd1; }
        }
        if (node0 < NN) { rmax_s = fmaxf(rmax_s, ss0); rmax_d = fmaxf(rmax_d, sd0); }
        if (node1 < NN) { rmax_s = fmaxf(rmax_s, ss1); rmax_d = fmaxf(rmax_d, sd1); }

#pragma unroll
        for (int nt = 0; nt < 8; nt++) {
            int pidx = qid + nt * 4;
            if (node0 < NN) {
                __half2 h0 = __floats2half2_rn(c[mt][nt][0], c[mt][nt][1]);
                g_whh[(size_t)node0 * 32 + pidx] = *reinterpret_cast<unsigned*>(&h0);
            }
            if (node1 < NN) {
                __half2 h1 = __floats2half2_rn(c[mt][nt][2], c[mt][nt][3]);
                g_whh[(size_t)node1 * 32 + pidx] = *reinterpret_cast<unsigned*>(&h1);
            }
        }
    }

#pragma unroll
    for (int o = 16; o; o >>= 1) {
        rmax_s = fmaxf(rmax_s, __shfl_xor_sync(0xffffffffu, rmax_s, o));
        rmax_d = fmaxf(rmax_d, __shfl_xor_sync(0xffffffffu, rmax_d, o));
    }
    __shared__ float sms[8], smd[8];
    if (lane == 0) { sms[w] = rmax_s; smd[w] = rmax_d; }
    __syncthreads();
    if (tid == 0) {
        float a = sms[0], b = smd[0];
        for (int i = 1; i < 8; i++) { a = fmaxf(a, sms[i]); b = fmaxf(b, smd[i]); }
        g_pmax_s[blockIdx.x] = a;
        g_pmax_d[blockIdx.x] = b;
    }
}

// ---------------- CSR aggregation (unchanged) ----------------
__global__ void __launch_bounds__(ETPB) k_aggr(int layer) {
    __shared__ float sB;
    {
        float a = -3.4e38f, b = -3.4e38f;
        for (int i = threadIdx.x; i < NBG; i += ETPB) {
            a = fmaxf(a, g_pmax_s[i]);
            b = fmaxf(b, g_pmax_d[i]);
        }
#pragma unroll
        for (int o = 16; o; o >>= 1) {
            a = fmaxf(a, __shfl_xor_sync(0xffffffffu, a, o));
            b = fmaxf(b, __shfl_xor_sync(0xffffffffu, b, o));
        }
        __shared__ float ra[EWPB], rb[EWPB];
        if ((threadIdx.x & 31) == 0) { ra[threadIdx.x >> 5] = a; rb[threadIdx.x >> 5] = b; }
        __syncthreads();
        if (threadIdx.x == 0) {
            float ma = ra[0], mb = rb[0];
            for (int i = 1; i < EWPB; i++) { ma = fmaxf(ma, ra[i]); mb = fmaxf(mb, rb[i]); }
            sB = ma + mb;
        }
        __syncthreads();
    }
    const float B = sB;

    int lane = threadIdx.x & 31;
    int wid = threadIdx.x >> 5;

    float2* acc2 = reinterpret_cast<float2*>(layer ? g_hacc : g_h1);

    float psum = 0.0f;
    for (int d = blockIdx.x * EWPB + wid; d < NN; d += EWARPS) {
        int beg = g_rowptr[d];
        int end = g_rowptr[d + 1];
        float sdd = g_sdst[d];
        float2 A0 = make_float2(0.f, 0.f), A1 = A0;

        for (int c = beg; c < end; c += 32) {
            int e = c + lane;
            int s = 0; float p = 0.f;
            if (e < end) {
                s = g_csrc[e];
                float sc = g_ssrc[s] + sdd;
                if (sc > 0.f) p = expf(sc - B);
            }
            psum += p;

            unsigned act = __ballot_sync(0xffffffffu, p != 0.f);
            while (act) {
                int j0 = __ffs(act) - 1; act &= act - 1;
                int s0 = __shfl_sync(0xffffffffu, s, j0);
                float p0 = __shfl_sync(0xffffffffu, p, j0);
                if (act) {
                    int j1 = __ffs(act) - 1; act &= act - 1;
                    int s1 = __shfl_sync(0xffffffffu, s, j1);
                    float p1 = __shfl_sync(0xffffffffu, p, j1);
                    unsigned u0 = g_whh[(size_t)s0 * 32 + lane];
                    unsigned u1 = g_whh[(size_t)s1 * 32 + lane];
                    float2 x0 = __half22float2(*reinterpret_cast<__half2*>(&u0));
                    float2 x1 = __half22float2(*reinterpret_cast<__half2*>(&u1));
                    A0.x += p0 * x0.x; A0.y += p0 * x0.y;
                    A1.x += p1 * x1.x; A1.y += p1 * x1.y;
                } else {
                    unsigned u0 = g_whh[(size_t)s0 * 32 + lane];
                    float2 x0 = __half22float2(*reinterpret_cast<__half2*>(&u0));
                    A0.x += p0 * x0.x; A0.y += p0 * x0.y;
                }
            }
        }

        float2 R;
        R.x = A0.x + A1.x;
        R.y = A0.y + A1.y;
        acc2[(size_t)d * 32 + lane] = R;
    }

#pragma unroll
    for (int o = 16; o; o >>= 1) psum += __shfl_xor_sync(0xffffffffu, psum, o);
    __shared__ float sm2[EWPB];
    if (lane == 0) sm2[wid] = psum;
    __syncthreads();
    if (threadIdx.x == 0) {
        float t = 0.0f;
        for (int i = 0; i < EWPB; i++) t += sm2[i];
        g_psum[blockIdx.x] = t;
    }
}

// ---------------- output head via tensor cores ----------------
__global__ void __launch_bounds__(NTPB, 2) k_out(const float* __restrict__ W,
                                                 const float* __restrict__ b,
                                                 float* __restrict__ out) {
    __shared__ __half sH[256 * HSTRIDE];
    __shared__ __half sWt[NC * HSTRIDE];   // 40 rows of K=64
    __shared__ float sb[NC];
    __shared__ float sInv;
    int tid = threadIdx.x;
    if (tid < NC) sb[tid] = b[tid];
    {
        float t = 0.0f;
        for (int i = tid; i < EGRID; i += NTPB) t += g_psum[i];
#pragma unroll
        for (int o = 16; o; o >>= 1) t += __shfl_xor_sync(0xffffffffu, t, o);
        __shared__ float smr[8];
        if ((tid & 31) == 0) smr[tid >> 5] = t;
        __syncthreads();
        if (tid == 0) {
            float s = 0.0f;
            for (int i = 0; i < 8; i++) s += smr[i];
            sInv = (s > 0.0f) ? (1.0f / s) : 0.0f;
        }
        __syncthreads();
    }
    float inv = sInv;

    // stage W^T (W is [64,40] row-major) -> sWt[n*HSTRIDE + k]
    for (int i = tid; i < HIDD * NC; i += NTPB) {
        int k = i / NC, n = i % NC;
        sWt[n * HSTRIDE + k] = __float2half(W[i]);
    }

    // stage h tile (transform ELU(x*inv))
    {
        int node = blockIdx.x * 256 + tid;
        int nc = (node < NN) ? node : 0;
        const float4* hr = g_hacc + (size_t)nc * 16;
        __half2* dst = reinterpret_cast<__half2*>(sH + tid * HSTRIDE);
#pragma unroll
        for (int k4 = 0; k4 < 16; k4++) {
            float4 v = hr[k4];
            v.x = eluf(v.x * inv); v.y = eluf(v.y * inv);
            v.z = eluf(v.z * inv); v.w = eluf(v.w * inv);
            dst[2 * k4]     = __floats2half2_rn(v.x, v.y);
            dst[2 * k4 + 1] = __floats2half2_rn(v.z, v.w);
        }
    }
    __syncthreads();

    int wp = tid >> 5;
    int lane = tid & 31;
    int grp = lane >> 2;
    int qid = lane & 3;

    float c[2][5][4];
#pragma unroll
    for (int mt = 0; mt < 2; mt++)
#pragma unroll
        for (int nt = 0; nt < 5; nt++)
#pragma unroll
            for (int q = 0; q < 4; q++) c[mt][nt][q] = 0.f;

#pragma unroll
    for (int kc = 0; kc < 4; kc++) {
        int k0 = kc * 16 + 2 * qid;
        unsigned a[2][4];
#pragma unroll
        for (int mt = 0; mt < 2; mt++) {
            const __half* base = sH + (wp * 32 + mt * 16 + grp) * HSTRIDE;
            a[mt][0] = *reinterpret_cast<const unsigned*>(base + k0);
            a[mt][1] = *reinterpret_cast<const unsigned*>(base + 8 * HSTRIDE + k0);
            a[mt][2] = *reinterpret_cast<const unsigned*>(base + k0 + 8);
            a[mt][3] = *reinterpret_cast<const unsigned*>(base + 8 * HSTRIDE + k0 + 8);
        }
#pragma unroll
        for (int nt = 0; nt < 5; nt++) {
            const __half* bb = sWt + (nt * 8 + grp) * HSTRIDE + k0;
            unsigned b0 = *reinterpret_cast<const unsigned*>(bb);
            unsigned b1 = *reinterpret_cast<const unsigned*>(bb + 8);
            mma16816(c[0][nt], a[0], b0, b1);
            mma16816(c[1][nt], a[1], b0, b1);
        }
    }

    // epilogue: +bias, ELU, log-softmax over row (qid-group reduce), store
    float2* of2 = reinterpret_cast<float2*>(out);
#pragma unroll
    for (int mt = 0; mt < 2; mt++) {
        int row0 = wp * 32 + mt * 16 + grp;
        int row1 = row0 + 8;
        int node0 = blockIdx.x * 256 + row0;
        int node1 = blockIdx.x * 256 + row1;

        float v0[10], v1[10];
#pragma unroll
        for (int nt = 0; nt < 5; nt++) {
            int col = nt * 8 + 2 * qid;
            float b0v = sb[col], b1v = sb[col + 1];
            v0[2 * nt]     = c[mt][nt][0] + b0v;
            v0[2 * nt + 1] = c[mt][nt][1] + b1v;
            v1[2 * nt]     = c[mt][nt][2] + b0v;
            v1[2 * nt + 1] = c[mt][nt][3] + b1v;
        }
        float m0 = -3.4e38f, m1 = -3.4e38f;
#pragma unroll
        for (int j = 0; j < 10; j++) {
            v0[j] = (v0[j] > 0.f) ? v0[j] : (expf(v0[j]) - 1.f);
            v1[j] = (v1[j] > 0.f) ? v1[j] : (expf(v1[j]) - 1.f);
            m0 = fmaxf(m0, v0[j]);
            m1 = fmaxf(m1, v1[j]);
        }
        m0 = fmaxf(m0, __shfl_xor_sync(0xffffffffu, m0, 1));
        m0 = fmaxf(m0, __shfl_xor_sync(0xffffffffu, m0, 2));
        m1 = fmaxf(m1, __shfl_xor_sync(0xffffffffu, m1, 1));
        m1 = fmaxf(m1, __shfl_xor_sync(0xffffffffu, m1, 2));

        float se0 = 0.f, se1 = 0.f;
#pragma unroll
        for (int j = 0; j < 10; j++) {
            se0 += expf(v0[j] - m0);
            se1 += expf(v1[j] - m1);
        }
        se0 += __shfl_xor_sync(0xffffffffu, se0, 1);
        se0 += __shfl_xor_sync(0xffffffffu, se0, 2);
        se1 += __shfl_xor_sync(0xffffffffu, se1, 1);
        se1 += __shfl_xor_sync(0xffffffffu, se1, 2);
        float lse0 = m0 + logf(se0);
        float lse1 = m1 + logf(se1);

#pragma unroll
        for (int nt = 0; nt < 5; nt++) {
            int pidx = nt * 4 + qid;   // float2 index within row of 20
            if (node0 < NN)
                of2[(size_t)node0 * 20 + pidx] = make_float2(v0[2 * nt] - lse0, v0[2 * nt + 1] - lse0);
            if (node1 < NN)
                of2[(size_t)node1 * 20 + pidx] = make_float2(v1[2 * nt] - lse1, v1[2 * nt + 1] - lse1);
        }
    }
}

// ---------------- launch ----------------
extern "C" void kernel_launch(void* const* d_in, const int* in_sizes, int n_in,
                              void* d_out, int out_size) {
    const float* x      = (const float*)d_in[0];
    const void*  ei     = (const void*)d_in[1];
    const float* emb_w  = (const float*)d_in[2];
    const float* emb_b  = (const float*)d_in[3];
    const float* Ws     = (const float*)d_in[4];
    const float* attn_a = (const float*)d_in[5];
    const float* out_w  = (const float*)d_in[6];
    const float* out_b  = (const float*)d_in[7];
    float* out          = (float*)d_out;

    (void)in_sizes; (void)n_in; (void)out_size;

    const int EB = (EE + 255) / 256;
    const int NB = (NN + 255) / 256;

    // order chosen so launch #6 (ncu -s 5 -c 1) is k_gemm_s(layer 0)
    k_emb<<<NBG, NTPB>>>(x, emb_w, emb_b);                       // 0
    k_detect_zdeg<<<NB, 256>>>((const int*)ei);                  // 1
    k_hist<<<EB, 256>>>(ei);                                     // 2
    k_scan1<<<SCAN_BLKS, 256>>>();                               // 3
    k_scan2<<<1, 512>>>();                                       // 4
    k_gemm_s<<<NBG, NTPB>>>(0, Ws, attn_a);                      // 5  <- profiled
    k_scan3<<<NB, 256>>>();                                      // 6
    k_scat<<<EB, 256>>>();                                       // 7
    k_aggr<<<EGRID, ETPB>>>(0);                                  // 8
    k_gemm_s<<<NBG, NTPB>>>(1, Ws + HIDD * HIDD, attn_a + 2 * HIDD); // 9
    k_aggr<<<EGRID, ETPB>>>(1);                                  // 10
    k_out<<<NBG, NTPB>>>(out_w, out_b, out);                     // 11
}